// round 12
// baseline (speedup 1.0000x reference)
#include <cuda_runtime.h>
#include <cuda_fp16.h>
#include <math.h>
#include <stdint.h>

// ---------------- fixed problem shapes ----------------
#define B_    4
#define SEQ   2048
#define PAST  2048
#define EDIM  1024
#define LDIM  1024
#define STOT  4096
#define QSCALE 0.022097086912079608f   // 1/sqrt(2*LDIM)

// ---------------- scratch (device globals) ----------------
__device__ __align__(256) __half g_xh   [(size_t)B_*SEQ*EDIM];
__device__ __align__(256) __half g_Wqh  [EDIM*EDIM];
__device__ __align__(256) __half g_Wukh [LDIM*EDIM];
__device__ __align__(256) __half g_Wdkvh[LDIM*EDIM];
__device__ __align__(256) __half g_Wkrh [LDIM*EDIM];
__device__ __align__(256) __half g_Wqrh [EDIM*LDIM];
__device__ __align__(256) __half g_Woh  [EDIM*EDIM];
__device__ __align__(256) __half g_WuvTh[EDIM*LDIM];
__device__ __align__(256) __half g_absTh[LDIM*EDIM];
__device__ __align__(256) float  g_c    [(size_t)B_*SEQ*LDIM];
__device__ __align__(256) float  g_krp  [(size_t)B_*SEQ*LDIM];
__device__ __align__(256) float  g_qpre [(size_t)B_*SEQ*EDIM];
__device__ __align__(256) __half g_Kcat [(size_t)B_*STOT*2048];   // [ckv | kr] fp16
__device__ __align__(256) __half g_Qcat [(size_t)B_*SEQ*2048];    // [xa | q_r] fp16
__device__ __align__(256) float  g_sc   [(size_t)B_*SEQ*STOT];
__device__ __align__(256) __half g_wh   [(size_t)B_*SEQ*STOT];
__device__ __align__(256) __half g_vTh  [(size_t)B_*EDIM*STOT];   // value^T per batch [E,S]
__device__ __align__(256) __half g_atth [(size_t)B_*SEQ*EDIM];

// ================= GEMM config =================
// Persistent warp-specialized cg2 GEMM. Pair computes M=256 x N=256 tiles,
// double-buffered TMEM accumulators (cols 0-255 / 256-511).
// Per CTA per stage: A half 16KB + B half 16KB = 32KB.
#define BK 64
#define NSTG 4
#define STAGE_BYTES 32768
#define GEMM_THREADS 416            // 8 producer + 1 mma/fwd + 4 epilogue warps
#define GEMM_SMEM (NSTG*STAGE_BYTES + 1024 + 128)
#define GEMM_GRID 148               // 74 persistent cluster pairs

// arch-specific feature gate: tcgen05 needs sm_103a / sm_100a compilation
#if defined(__CUDA_ARCH__) && (defined(__CUDA_ARCH_FEAT_SM103_ALL) || defined(__CUDA_ARCH_FEAT_SM100_ALL) || defined(__CUDA_ARCH_FEAT_SM101_ALL))
#define USE_TCGEN05 1
#else
#define USE_TCGEN05 0
#endif

__device__ __forceinline__ void cp_async16(uint32_t dst, const void* src) {
    asm volatile("cp.async.cg.shared.global [%0], [%1], 16;" :: "r"(dst), "l"(src) : "memory");
}

#if USE_TCGEN05
__device__ __forceinline__ uint32_t sw128(uint32_t o) { return o ^ ((o >> 3) & 0x70u); }

__device__ __forceinline__ uint64_t make_desc(uint32_t addr) {
    return ((uint64_t)2 << 61) | (1ull << 46) | (64ull << 32) | (1ull << 16)
         | ((addr >> 4) & 0x3FFFull);
}

__device__ __forceinline__ bool elect_one() {
    uint32_t pred;
    asm volatile("{\n\t.reg .pred p;\n\telect.sync _|p, 0xFFFFFFFF;\n\tselp.b32 %0, 1, 0, p;\n\t}"
                 : "=r"(pred));
    return pred != 0;
}

__device__ __forceinline__ void mbar_init(uint32_t a, uint32_t cnt) {
    asm volatile("mbarrier.init.shared.b64 [%0], %1;" :: "r"(a), "r"(cnt) : "memory");
}

__device__ __forceinline__ void mbar_wait(uint32_t a, uint32_t ph) {
    asm volatile(
        "{\n\t.reg .pred P;\n"
        "LW%=:\n\t"
        "mbarrier.try_wait.parity.acquire.cta.shared::cta.b64 P, [%0], %1, 0x989680;\n\t"
        "@!P bra LW%=;\n\t}"
        :: "r"(a), "r"(ph) : "memory");
}

__device__ __forceinline__ void cp_async_arrive(uint32_t bar) {
    asm volatile("cp.async.mbarrier.arrive.noinc.shared::cta.b64 [%0];" :: "r"(bar) : "memory");
}

// arrive on leader (rank 0) CTA's mbarrier at the same smem offset
__device__ __forceinline__ void mbar_arrive_leader(uint32_t local_addr) {
    asm volatile(
        "{\n\t.reg .b32 remAddr;\n\t"
        "mapa.shared::cluster.u32 remAddr, %0, 0;\n\t"
        "mbarrier.arrive.shared::cluster.b64 _, [remAddr];\n\t}"
        :: "r"(local_addr) : "memory");
}

__device__ __forceinline__ void mma_f16_cg2(uint32_t d, uint64_t ad, uint64_t bd,
                                            uint32_t idesc, uint32_t en) {
    asm volatile(
        "{\n\t.reg .pred p;\n\tsetp.ne.u32 p, %4, 0;\n\t"
        "tcgen05.mma.cta_group::2.kind::f16 [%0], %1, %2, %3, "
        "{%5, %5, %5, %5, %5, %5, %5, %5}, p;\n\t}"
        :: "r"(d), "l"(ad), "l"(bd), "r"(idesc), "r"(en), "r"(0u) : "memory");
}

__device__ __forceinline__ void tc_commit_mc2(uint32_t bar) {
    asm volatile(
        "tcgen05.commit.cta_group::2.mbarrier::arrive::one.shared::cluster.multicast::cluster.b64 [%0], %1;"
        :: "r"(bar), "h"((uint16_t)3) : "memory");
}

__device__ __forceinline__ void ldtm32(uint32_t* r, uint32_t addr) {
    asm volatile(
        "tcgen05.ld.sync.aligned.32x32b.x32.b32 "
        "{%0, %1, %2, %3, %4, %5, %6, %7, "
        " %8, %9, %10, %11, %12, %13, %14, %15, "
        " %16, %17, %18, %19, %20, %21, %22, %23, "
        " %24, %25, %26, %27, %28, %29, %30, %31}, [%32];"
        : "=r"(r[0]),  "=r"(r[1]),  "=r"(r[2]),  "=r"(r[3]),
          "=r"(r[4]),  "=r"(r[5]),  "=r"(r[6]),  "=r"(r[7]),
          "=r"(r[8]),  "=r"(r[9]),  "=r"(r[10]), "=r"(r[11]),
          "=r"(r[12]), "=r"(r[13]), "=r"(r[14]), "=r"(r[15]),
          "=r"(r[16]), "=r"(r[17]), "=r"(r[18]), "=r"(r[19]),
          "=r"(r[20]), "=r"(r[21]), "=r"(r[22]), "=r"(r[23]),
          "=r"(r[24]), "=r"(r[25]), "=r"(r[26]), "=r"(r[27]),
          "=r"(r[28]), "=r"(r[29]), "=r"(r[30]), "=r"(r[31])
        : "r"(addr));
}
#endif  // USE_TCGEN05

// Persistent GEMM: C[z][M,N] = A[z][M,K] * B[z][N,K]^T, fp16 in, fp32 accum.
// M%256==0, N%256==0, K%64==0. Grid = GEMM_GRID CTAs (74 cg2 pairs), each pair
// strides over Z*(M/256)*(N/256) tiles. cflag bit0: causal tile skip;
// bit1: causal K-limit.
template<bool OUT_HALF>
__global__ void __launch_bounds__(GEMM_THREADS, 1) __cluster_dims__(2, 1, 1)
hgemm(const __half* __restrict__ A, const __half* __restrict__ Bm, void* __restrict__ Cv,
      int M, int N, int K, long long sA, long long sB, long long sC,
      int lda, int ldb, int ldc, int cflag, int Z)
{
    extern __shared__ char dynsmem[];
    const int tid  = threadIdx.x;
    const int wid  = tid >> 5;
    const int rank = blockIdx.x & 1;
    const int pairId = blockIdx.x >> 1;
    const int nPairs = gridDim.x >> 1;
    const int nN = N >> 8;
    const int tilesPerZ = (M >> 8) * nN;
    const int totalTiles = Z * tilesPerZ;

#if USE_TCGEN05
    uint32_t raw  = (uint32_t)__cvta_generic_to_shared(dynsmem);
    uint32_t tb   = (raw + 1023u) & ~1023u;
    uint32_t ctrl = tb + NSTG * STAGE_BYTES;
    // ctrl+0 tmem; full[s]=ctrl+8+8s; empty[s]=ctrl+40+8s; done[b]=ctrl+72+8b; free[b]=ctrl+88+8b

    if (tid == 0) {
        #pragma unroll
        for (int s = 0; s < NSTG; s++) {
            mbar_init(ctrl + 8  + 8*s, (rank == 0) ? 257u : 256u);
            mbar_init(ctrl + 40 + 8*s, 1);
        }
        mbar_init(ctrl + 72, 1); mbar_init(ctrl + 80, 1);
        mbar_init(ctrl + 88, 8); mbar_init(ctrl + 96, 8);
    }
    __syncthreads();
    if (wid == 8) {
        asm volatile("tcgen05.alloc.cta_group::2.sync.aligned.shared::cta.b32 [%0], %1;"
                     :: "r"(ctrl), "r"(512u) : "memory");
        asm volatile("tcgen05.relinquish_alloc_permit.cta_group::2.sync.aligned;");
    }
    __syncthreads();
    asm volatile("barrier.cluster.arrive.aligned;" ::: "memory");
    asm volatile("barrier.cluster.wait.aligned;"   ::: "memory");

    uint32_t tmem;
    asm volatile("ld.shared.b32 %0, [%1];" : "=r"(tmem) : "r"(ctrl));

    if (wid < 8) {
        // ================= producers: continuous cp.async stream =================
        const int r0  = tid >> 3;
        const int c16 = tid & 7;
        uint32_t sw[4];
        #pragma unroll
        for (int i = 0; i < 4; i++) sw[i] = sw128((uint32_t)((r0 + 32*i) * 128 + c16 * 16));
        const long long la32 = (long long)lda * 32, lb32 = (long long)ldb * 32;

        int s = 0; uint32_t phE = 1;
        for (int t = pairId; t < totalTiles; t += nPairs) {
            const int z = t / tilesPerZ, r = t - z * tilesPerZ;
            const int m0 = (r / nN) << 8, n0 = (r % nN) << 8;
            if ((cflag & 1) && n0 >= m0 + 256 + PAST) continue;
            int nCh = K >> 6;
            if (cflag & 2) { int lim = (m0 + 256 + PAST) >> 6; if (lim < nCh) nCh = lim; }
            const __half* ap = A  + z * sA + (long long)(m0 + rank*128 + r0) * lda + c16 * 8;
            const __half* bp = Bm + z * sB + (long long)(n0 + rank*128 + r0) * ldb + c16 * 8;
            for (int kc = 0; kc < nCh; kc++) {
                mbar_wait(ctrl + 40 + 8*s, phE);
                uint32_t sb = tb + s * STAGE_BYTES;
                #pragma unroll
                for (int i = 0; i < 4; i++) cp_async16(sb + sw[i],          ap + i * la32);
                #pragma unroll
                for (int i = 0; i < 4; i++) cp_async16(sb + 16384u + sw[i], bp + i * lb32);
                cp_async_arrive(ctrl + 8 + 8*s);
                ap += BK; bp += BK;
                if (++s == NSTG) { s = 0; phE ^= 1; }
            }
        }
    } else if (wid == 8 && rank == 0) {
        // ================= leader MMA warp =================
        const uint32_t idesc = (1u << 4) | (32u << 17) | (16u << 24);
        int s = 0; uint32_t phF = 0;
        uint32_t phFree0 = 1, phFree1 = 1;
        int tc = 0;
        for (int t = pairId; t < totalTiles; t += nPairs) {
            const int z = t / tilesPerZ, r = t - z * tilesPerZ;
            const int m0 = (r / nN) << 8, n0 = (r % nN) << 8;
            if ((cflag & 1) && n0 >= m0 + 256 + PAST) continue;
            int nCh = K >> 6;
            if (cflag & 2) { int lim = (m0 + 256 + PAST) >> 6; if (lim < nCh) nCh = lim; }
            const int buf = tc & 1;
            if (buf == 0) { mbar_wait(ctrl + 88, phFree0); phFree0 ^= 1; }
            else          { mbar_wait(ctrl + 96, phFree1); phFree1 ^= 1; }
            const uint32_t dtm = tmem + buf * 256u;
            for (int kc = 0; kc < nCh; kc++) {
                mbar_wait(ctrl + 8 + 8*s, phF);
                if (elect_one()) {
                    asm volatile("fence.proxy.async.shared::cta;" ::: "memory");
                    uint64_t ad = make_desc(tb + s * STAGE_BYTES);
                    uint64_t bd = make_desc(tb + s * STAGE_BYTES + 16384);
                    #pragma unroll
                    for (int st = 0; st < 4; st++)
                        mma_f16_cg2(dtm, ad + st * 2, bd + st * 2, idesc,
                                    (kc == 0 && st == 0) ? 0u : 1u);
                    tc_commit_mc2(ctrl + 40 + 8*s);
                }
                if (++s == NSTG) { s = 0; phF ^= 1; }
            }
            if (elect_one()) tc_commit_mc2(ctrl + 72 + 8*buf);   // done[buf] -> both CTAs
            tc++;
        }
    } else if (wid == 8) {
        // ================= follower forward warp =================
        int s = 0; uint32_t phF = 0;
        for (int t = pairId; t < totalTiles; t += nPairs) {
            const int z = t / tilesPerZ, r = t - z * tilesPerZ;
            const int m0 = (r / nN) << 8, n0 = (r % nN) << 8;
            if ((cflag & 1) && n0 >= m0 + 256 + PAST) continue;
            int nCh = K >> 6;
            if (cflag & 2) { int lim = (m0 + 256 + PAST) >> 6; if (lim < nCh) nCh = lim; }
            for (int kc = 0; kc < nCh; kc++) {
                mbar_wait(ctrl + 8 + 8*s, phF);
                if (elect_one()) mbar_arrive_leader(ctrl + 8 + 8*s);
                if (++s == NSTG) { s = 0; phF ^= 1; }
            }
        }
    } else {
        // ================= epilogue warps (wid 9..12) =================
        // TMEM lane subpartition is wid % 4 (HW-fixed), so the row group MUST
        // be wid & 3: warp 9 -> rows 32-63, 10 -> 64-95, 11 -> 96-127, 12 -> 0-31.
        const int we = wid & 3;
        const int l = tid & 31;
        uint32_t phD0 = 0, phD1 = 0;
        int tc = 0;
        for (int t = pairId; t < totalTiles; t += nPairs) {
            const int z = t / tilesPerZ, r = t - z * tilesPerZ;
            const int m0 = (r / nN) << 8, n0 = (r % nN) << 8;
            if ((cflag & 1) && n0 >= m0 + 256 + PAST) continue;
            const int buf = tc & 1;
            if (buf == 0) { mbar_wait(ctrl + 72, phD0); phD0 ^= 1; }
            else          { mbar_wait(ctrl + 80, phD1); phD1 ^= 1; }
            asm volatile("tcgen05.fence::after_thread_sync;" ::: "memory");
            const uint32_t dtm = tmem + buf * 256u;
            const long long row = (long long)m0 + rank * 128 + we * 32 + l;
            if (OUT_HALF) {
                __half* C = (__half*)Cv + z * sC + row * ldc + n0;
                for (int b8 = 0; b8 < 8; b8++) {
                    uint32_t rg[32];
                    ldtm32(rg, dtm + b8 * 32);
                    asm volatile("tcgen05.wait::ld.sync.aligned;" ::: "memory");
                    uint32_t h[16];
                    #pragma unroll
                    for (int j = 0; j < 16; j++) {
                        __half2 hv = __floats2half2_rn(__uint_as_float(rg[2*j]), __uint_as_float(rg[2*j+1]));
                        h[j] = *reinterpret_cast<uint32_t*>(&hv);
                    }
                    uint4* dst = (uint4*)(C + b8 * 32);
                    #pragma unroll
                    for (int q = 0; q < 4; q++) dst[q] = make_uint4(h[4*q], h[4*q+1], h[4*q+2], h[4*q+3]);
                }
            } else {
                float* C = (float*)Cv + z * sC + row * ldc + n0;
                for (int b8 = 0; b8 < 8; b8++) {
                    uint32_t rg[32];
                    ldtm32(rg, dtm + b8 * 32);
                    asm volatile("tcgen05.wait::ld.sync.aligned;" ::: "memory");
                    float4* dst = (float4*)(C + b8 * 32);
                    #pragma unroll
                    for (int q = 0; q < 8; q++)
                        dst[q] = make_float4(__uint_as_float(rg[4*q]),   __uint_as_float(rg[4*q+1]),
                                             __uint_as_float(rg[4*q+2]), __uint_as_float(rg[4*q+3]));
                }
            }
            asm volatile("tcgen05.fence::before_thread_sync;" ::: "memory");
            if (elect_one()) {
                if (rank == 0)
                    asm volatile("mbarrier.arrive.shared.b64 _, [%0];" :: "r"(ctrl + 88 + 8*buf) : "memory");
                else
                    mbar_arrive_leader(ctrl + 88 + 8*buf);
            }
            tc++;
        }
    }

    __syncthreads();
    if (wid == 8)
        asm volatile("tcgen05.dealloc.cta_group::2.sync.aligned.b32 %0, %1;" :: "r"(tmem), "r"(512u));
    asm volatile("barrier.cluster.arrive.aligned;" ::: "memory");
    asm volatile("barrier.cluster.wait.aligned;"   ::: "memory");

#else
    // ===================== mma.sync fallback (plain sm_103), persistent =====================
    const int lane = tid & 31;
    const int g  = lane >> 2;
    const int tg = lane & 3;
    uint32_t sbase = (uint32_t)__cvta_generic_to_shared(dynsmem);
    sbase = (sbase + 127u) & ~127u;
    const uint32_t ST_A = 0, ST_B = 128 * 144, ST_SZ = 128 * 144 + 256 * 144;

    for (int t = pairId; t < totalTiles; t += nPairs) {
        const int z = t / tilesPerZ, r = t - z * tilesPerZ;
        const int m0 = (r / nN) << 8, n0 = (r % nN) << 8;
        if ((cflag & 1) && n0 >= m0 + 256 + PAST) continue;
        int nCh = K >> 6;
        if (cflag & 2) { int lim = (m0 + 256 + PAST) >> 6; if (lim < nCh) nCh = lim; }
        const __half* At = A  + z * sA;
        const __half* Bt = Bm + z * sB;
        const int m0h = m0 + rank * 128;

        auto load_stage = [&](int s, int kk) {
            uint32_t sb = sbase + (uint32_t)s * ST_SZ;
            for (int idx = tid; idx < 3072; idx += GEMM_THREADS) {
                if (idx < 1024) {
                    int row = idx >> 3, c = idx & 7;
                    cp_async16(sb + ST_A + row * 144 + c * 16,
                               At + (long long)(m0h + row) * lda + kk + c * 8);
                } else {
                    int j = idx - 1024;
                    int row = j >> 3, c = j & 7;
                    cp_async16(sb + ST_B + row * 144 + c * 16,
                               Bt + (long long)(n0 + row) * ldb + kk + c * 8);
                }
            }
            asm volatile("cp.async.commit_group;" ::: "memory");
        };

        const int wm = (wid >> 1) * 32;
        const int wn = (wid & 1) * 128;

        float acc[16][4];
        #pragma unroll
        for (int jn = 0; jn < 16; jn++)
            #pragma unroll
            for (int q = 0; q < 4; q++) acc[jn][q] = 0.f;

        load_stage(0, 0);
        for (int kc = 0; kc < nCh; kc++) {
            if (kc + 1 < nCh) {
                load_stage((kc + 1) & 1, (kc + 1) * BK);
                asm volatile("cp.async.wait_group 1;" ::: "memory");
            } else {
                asm volatile("cp.async.wait_group 0;" ::: "memory");
            }
            __syncthreads();

            if (wid < 8) {
                uint32_t sb = sbase + (uint32_t)(kc & 1) * ST_SZ;
                #pragma unroll
                for (int k0 = 0; k0 < 64; k0 += 16) {
                    uint32_t a[2][2];
                    {
                        uint32_t r0a = sb + ST_A + (uint32_t)(wm + g) * 144 + (uint32_t)(k0 + tg * 2) * 2;
                        asm volatile("ld.shared.b32 %0, [%1];"        : "=r"(a[0][0]) : "r"(r0a));
                        asm volatile("ld.shared.b32 %0, [%1 + 1152];" : "=r"(a[0][1]) : "r"(r0a));
                        asm volatile("ld.shared.b32 %0, [%1 + 16];"   : "=r"(a[1][0]) : "r"(r0a));
                        asm volatile("ld.shared.b32 %0, [%1 + 1168];" : "=r"(a[1][1]) : "r"(r0a));
                    }
                    #pragma unroll
                    for (int jn = 0; jn < 16; jn++) {
                        uint32_t b0, b1;
                        uint32_t rb = sb + ST_B + (uint32_t)(wn + jn * 8 + g) * 144 + (uint32_t)(k0 + tg * 2) * 2;
                        asm volatile("ld.shared.b32 %0, [%1];"      : "=r"(b0) : "r"(rb));
                        asm volatile("ld.shared.b32 %0, [%1 + 16];" : "=r"(b1) : "r"(rb));
                        asm volatile(
                            "mma.sync.aligned.m16n8k16.row.col.f32.f16.f16.f32 "
                            "{%0,%1,%2,%3}, {%4,%5,%6,%7}, {%8,%9}, {%0,%1,%2,%3};"
                            : "+f"(acc[jn][0]), "+f"(acc[jn][1]),
                              "+f"(acc[jn][2]), "+f"(acc[jn][3])
                            : "r"(a[0][0]), "r"(a[0][1]), "r"(a[1][0]), "r"(a[1][1]),
                              "r"(b0), "r"(b1));
                    }
                }
            }
            __syncthreads();
        }

        if (wid < 8) {
            const long long r0w = (long long)m0h + wm + g;
            #pragma unroll
            for (int jn = 0; jn < 16; jn++) {
                const long long cc = (long long)n0 + wn + jn * 8 + tg * 2;
                if (OUT_HALF) {
                    __half* C = (__half*)Cv + z * sC;
                    *(__half2*)(C + r0w * ldc + cc)       = __floats2half2_rn(acc[jn][0], acc[jn][1]);
                    *(__half2*)(C + (r0w + 8) * ldc + cc) = __floats2half2_rn(acc[jn][2], acc[jn][3]);
                } else {
                    float* C = (float*)Cv + z * sC;
                    float* p0 = C + r0w * ldc + cc;
                    float* p1 = C + (r0w + 8) * ldc + cc;
                    p0[0] = acc[jn][0]; p0[1] = acc[jn][1];
                    p1[0] = acc[jn][2]; p1[1] = acc[jn][3];
                }
            }
        }
        __syncthreads();
    }
#endif
}

// ================= elementwise kernels =================
__device__ __forceinline__ uint32_t h2bits(__half2 h) { return *reinterpret_cast<uint32_t*>(&h); }

__global__ void cvt_f32_f16(const float* __restrict__ in, __half* __restrict__ out, int n8) {
    int i = blockIdx.x * 256 + threadIdx.x;
    if (i < n8) {
        float4 a = ((const float4*)in)[2*i], b = ((const float4*)in)[2*i+1];
        uint4 o;
        o.x = h2bits(__floats2half2_rn(a.x, a.y));
        o.y = h2bits(__floats2half2_rn(a.z, a.w));
        o.z = h2bits(__floats2half2_rn(b.x, b.y));
        o.w = h2bits(__floats2half2_rn(b.z, b.w));
        ((uint4*)out)[i] = o;
    }
}

__global__ void cvt_weights6(const float* s0, const float* s1, const float* s2,
                             const float* s3, const float* s4, const float* s5,
                             __half* d0, __half* d1, __half* d2,
                             __half* d3, __half* d4, __half* d5) {
    int i = blockIdx.x * 256 + threadIdx.x;
    int w = i >> 17;
    int j = i & 131071;
    const float* s; __half* d;
    switch (w) {
        case 0: s = s0; d = d0; break;
        case 1: s = s1; d = d1; break;
        case 2: s = s2; d = d2; break;
        case 3: s = s3; d = d3; break;
        case 4: s = s4; d = d4; break;
        default: s = s5; d = d5; break;
    }
    const float sc = (w == 1 || w == 4) ? QSCALE : 1.0f;
    float4 a = ((const float4*)s)[2*j], b = ((const float4*)s)[2*j+1];
    uint4 o;
    o.x = h2bits(__floats2half2_rn(a.x * sc, a.y * sc));
    o.y = h2bits(__floats2half2_rn(a.z * sc, a.w * sc));
    o.z = h2bits(__floats2half2_rn(b.x * sc, b.y * sc));
    o.w = h2bits(__floats2half2_rn(b.z * sc, b.w * sc));
    ((uint4*)d)[j] = o;
}

__global__ void transpose_f32_f16(const float* __restrict__ in, __half* __restrict__ out, int R, int C) {
    __shared__ float t[32][33];
    int bx = blockIdx.x * 32, by = blockIdx.y * 32;
    #pragma unroll
    for (int j = 0; j < 32; j += 8)
        t[threadIdx.y + j][threadIdx.x] = in[(long long)(by + threadIdx.y + j) * C + bx + threadIdx.x];
    __syncthreads();
    #pragma unroll
    for (int j = 0; j < 32; j += 8)
        out[(long long)(bx + threadIdx.y + j) * R + by + threadIdx.x] =
            __float2half_rn(t[threadIdx.x][threadIdx.y + j]);
}

__global__ void copy_cache(const float* __restrict__ src, float* __restrict__ dstF,
                           __half* __restrict__ dstH, int hcol) {
    int row = blockIdx.x; int b = row / PAST, r = row % PAST;
    const float4* s  = (const float4*)(src + (size_t)row * 1024);
    float4* dF = (float4*)(dstF + ((size_t)b * STOT + r) * 1024);
    __half* dH = dstH + ((size_t)b * STOT + r) * 2048 + hcol;
    int j = threadIdx.x;
    float4 v = s[j];
    dF[j] = v;
    uint2 u; u.x = h2bits(__floats2half2_rn(v.x, v.y)); u.y = h2bits(__floats2half2_rn(v.z, v.w));
    *(uint2*)(dH + j * 4) = u;
}

__device__ __forceinline__ float blk_sum(float v, float* red) {
    const int tid = threadIdx.x;
    #pragma unroll
    for (int o = 16; o > 0; o >>= 1) v += __shfl_xor_sync(0xffffffffu, v, o);
    if ((tid & 31) == 0) red[tid >> 5] = v;
    __syncthreads();
    float t = (tid < 8) ? red[tid] : 0.f;
    if (tid < 32) {
        #pragma unroll
        for (int o = 4; o > 0; o >>= 1) t += __shfl_xor_sync(0xffffffffu, t, o);
        if (tid == 0) red[0] = t;
    }
    __syncthreads();
    float r = red[0];
    __syncthreads();
    return r;
}

__device__ __forceinline__ float blk_max(float v, float* red) {
    const int tid = threadIdx.x;
    #pragma unroll
    for (int o = 16; o > 0; o >>= 1) v = fmaxf(v, __shfl_xor_sync(0xffffffffu, v, o));
    if ((tid & 31) == 0) red[tid >> 5] = v;
    __syncthreads();
    float t = (tid < 8) ? red[tid] : -3.4e38f;
    if (tid < 32) {
        #pragma unroll
        for (int o = 4; o > 0; o >>= 1) t = fmaxf(t, __shfl_xor_sync(0xffffffffu, t, o));
        if (tid == 0) red[0] = t;
    }
    __syncthreads();
    float r = red[0];
    __syncthreads();
    return r;
}

__global__ void layernorm_kernel(const float* __restrict__ c, float* __restrict__ ckv,
                                 __half* __restrict__ kcat,
                                 const float* __restrict__ g, const float* __restrict__ b) {
    const int row = blockIdx.x; const int bb = row / SEQ, si = row % SEQ;
    const float* p = c + (size_t)row * LDIM;
    float*  o  = ckv  + ((size_t)bb * STOT + PAST + si) * 1024;
    __half* oh = kcat + ((size_t)bb * STOT + PAST + si) * 2048;
    __shared__ float red[8];
    const int tid = threadIdx.x;
    float s = 0.f, s2 = 0.f;
    for (int j = tid; j < LDIM; j += 256) { float v = p[j]; s += v; s2 += v * v; }
    s  = blk_sum(s,  red);
    s2 = blk_sum(s2, red);
    const float mean = s * (1.f / LDIM);
    const float var  = fmaxf(s2 * (1.f / LDIM) - mean * mean, 0.f);
    const float inv  = rsqrtf(var + 1e-5f);
    for (int j = tid; j < LDIM; j += 256) {
        float v = (p[j] - mean) * inv * g[j] + b[j];
        o[j] = v; oh[j] = __float2half_rn(v);
    }
}

__global__ void rope_k_kernel(const float* __restrict__ in, float* __restrict__ kr,
                              __half* __restrict__ kcat) {
    const int row = blockIdx.x; const int bb = row / SEQ, t = row % SEQ;
    const int j = threadIdx.x;
    const float* pi = in + (size_t)row * 1024;
    float*  po = kr   + ((size_t)bb * STOT + PAST + t) * 1024;
    __half* ph = kcat + ((size_t)bb * STOT + PAST + t) * 2048 + 1024;
    float x1 = pi[j], x2 = pi[j + 512];
    const float inv_freq = powf(10000.f, -(float)(2 * j) * (1.f / 1024.f));
    float sn, cs; sincosf((float)t * inv_freq, &sn, &cs);
    float y1 = x1 * cs - x2 * sn, y2 = x2 * cs + x1 * sn;
    po[j] = y1; po[j + 512] = y2;
    ph[j] = __float2half_rn(y1); ph[j + 512] = __float2half_rn(y2);
}

__global__ void rope_q_kernel(const float* __restrict__ in, __half* __restrict__ qcat,
                              const float* __restrict__ bias) {
    const int row = blockIdx.x; const int t = row % SEQ;
    const int j = threadIdx.x;
    const float* pi = in + (size_t)row * 1024;
    __half* ph = qcat + (size_t)row * 2048 + 1024;
    float x1 = pi[j] + QSCALE * bias[j], x2 = pi[j + 512] + QSCALE * bias[j + 512];
    const float inv_freq = powf(10000.f, -(float)(2 * j) * (1.f / 1024.f));
    float sn, cs; sincosf((float)t * inv_freq, &sn, &cs);
    ph[j]       = __float2half_rn(x1 * cs - x2 * sn);
    ph[j + 512] = __float2half_rn(x2 * cs + x1 * sn);
}

__global__ void softmax_kernel(const float* __restrict__ sc, __half* __restrict__ wh) {
    const int row = blockIdx.x;
    const int si  = row % SEQ;
    const int valid = si + PAST + 1;
    const float* p = sc + (size_t)row * STOT;
    __half* o = wh + (size_t)row * STOT;
    __shared__ float buf[STOT];
    __shared__ float red[8];
    const int tid = threadIdx.x;

    float mx = -3.4e38f;
    for (int j = tid; j < valid; j += 256) { float v = p[j]; buf[j] = v; mx = fmaxf(mx, v); }
    mx = blk_max(mx, red);
    float sum = 0.f;
    for (int j = tid; j < valid; j += 256) { float e = __expf(buf[j] - mx); buf[j] = e; sum += e; }
    sum = blk_sum(sum, red);
    const float inv = 1.f / sum;
    for (int j = tid; j < valid; j += 256) o[j] = __float2half_rn(buf[j] * inv);
    for (int j = valid + tid; j < STOT; j += 256) o[j] = __float2half_rn(0.f);
}

// ================= launch =================
extern "C" void kernel_launch(void* const* d_in, const int* in_sizes, int n_in,
                              void* d_out, int out_size)
{
    (void)in_sizes; (void)n_in; (void)out_size;
    const float* x        = (const float*)d_in[0];
    const float* kv_cache = (const float*)d_in[1];
    const float* kr_cache = (const float*)d_in[2];
    const float* Wq       = (const float*)d_in[3];
    const float* Wdkv     = (const float*)d_in[4];
    const float* Wuk      = (const float*)d_in[5];
    const float* Wuv      = (const float*)d_in[6];
    const float* Wo       = (const float*)d_in[7];
    const float* Wkr      = (const float*)d_in[8];
    const float* Wqr      = (const float*)d_in[9];
    const float* bqr      = (const float*)d_in[10];
    const float* ln_g     = (const float*)d_in[11];
    const float* ln_b     = (const float*)d_in[12];

    float* out = (float*)d_out;
    float* ckv = out + (size_t)B_ * SEQ * EDIM;
    float* kr  = ckv + (size_t)B_ * STOT * LDIM;

    __half *xh, *wqh, *wukh, *wdkvh, *wkrh, *wqrh, *woh, *wuvTh, *absTh, *Kcat, *Qcat, *wh, *vTh, *atth;
    float *c, *krp, *qpre, *sc;
    cudaGetSymbolAddress((void**)&xh,    g_xh);
    cudaGetSymbolAddress((void**)&wqh,   g_Wqh);
    cudaGetSymbolAddress((void**)&wukh,  g_Wukh);
    cudaGetSymbolAddress((void**)&wdkvh, g_Wdkvh);
    cudaGetSymbolAddress((void**)&wkrh,  g_Wkrh);
    cudaGetSymbolAddress((void**)&wqrh,  g_Wqrh);
    cudaGetSymbolAddress((void**)&woh,   g_Woh);
    cudaGetSymbolAddress((void**)&wuvTh, g_WuvTh);
    cudaGetSymbolAddress((void**)&absTh, g_absTh);
    cudaGetSymbolAddress((void**)&c,     g_c);
    cudaGetSymbolAddress((void**)&krp,   g_krp);
    cudaGetSymbolAddress((void**)&qpre,  g_qpre);
    cudaGetSymbolAddress((void**)&Kcat,  g_Kcat);
    cudaGetSymbolAddress((void**)&Qcat,  g_Qcat);
    cudaGetSymbolAddress((void**)&sc,    g_sc);
    cudaGetSymbolAddress((void**)&wh,    g_wh);
    cudaGetSymbolAddress((void**)&vTh,   g_vTh);
    cudaGetSymbolAddress((void**)&atth,  g_atth);

    cudaFuncSetAttribute(hgemm<false>, cudaFuncAttributeMaxDynamicSharedMemorySize, GEMM_SMEM);
    cudaFuncSetAttribute(hgemm<true>,  cudaFuncAttributeMaxDynamicSharedMemorySize, GEMM_SMEM);

    // ---- proven topology: 3 streams, 9 events, single-use ----
    static cudaStream_t st[3] = {nullptr, nullptr, nullptr};
    static cudaEvent_t  ev[10] = {};
    if (st[0] == nullptr) {
        for (int i = 0; i < 3; i++) cudaStreamCreateWithFlags(&st[i], cudaStreamNonBlocking);
        for (int i = 0; i < 10; i++) cudaEventCreateWithFlags(&ev[i], cudaEventDisableTiming);
    }
    cudaEvent_t eFork = ev[0], eX = ev[1], eW = ev[2], eXa = ev[3], eT = ev[4],
                eRk = ev[5], eCc = ev[6], eLN = ev[7], eV = ev[8];

    const long long sL2 = (long long)SEQ * 2048;
    const long long SL2 = (long long)STOT * 2048;
    const long long sS  = (long long)SEQ * STOT;
    const long long sE  = (long long)SEQ * 1024;
    const long long ES  = (long long)EDIM * STOT;
    const dim3 PG(GEMM_GRID, 1, 1);

    // ---------------- FORK ----------------
    cudaEventRecord(eFork, 0);
    for (int i = 0; i < 3; i++) cudaStreamWaitEvent(st[i], eFork, 0);

    cvt_f32_f16<<<4096, 256>>>(x, xh, (B_*SEQ*EDIM)/8);
    cudaEventRecord(eX, 0);

    // st[0]: weights cvt -> absT -> xa (Qcat left)
    cvt_weights6<<<3072, 256, 0, st[0]>>>(Wq, Wuk, Wdkv, Wkr, Wqr, Wo,
                                          wqh, wukh, wdkvh, wkrh, wqrh, woh);
    cudaEventRecord(eW, st[0]);
    hgemm<true><<<PG, GEMM_THREADS, GEMM_SMEM, st[0]>>>(
        wukh, wqh, absTh, 1024, 1024, 1024, 0, 0, 0, 1024, 1024, 1024, 0, 1);
    cudaStreamWaitEvent(st[0], eX, 0);
    hgemm<true><<<PG, GEMM_THREADS, GEMM_SMEM, st[0]>>>(
        xh, absTh, Qcat, 8192, 1024, 1024, 0, 0, 0, 1024, 1024, 2048, 0, 1);
    cudaEventRecord(eXa, st[0]);

    // st[1]: Wuv transpose, then krp -> rope_k
    transpose_f32_f16<<<dim3(32, 32), dim3(32, 8), 0, st[1]>>>(Wuv, wuvTh, LDIM, EDIM);
    cudaEventRecord(eT, st[1]);
    cudaStreamWaitEvent(st[1], eX, 0);
    cudaStreamWaitEvent(st[1], eW, 0);
    hgemm<false><<<PG, GEMM_THREADS, GEMM_SMEM, st[1]>>>(
        xh, wkrh, krp, 8192, 1024, 1024, 0, 0, 0, 1024, 1024, 1024, 0, 1);
    rope_k_kernel<<<B_*SEQ, 512, 0, st[1]>>>(krp, kr, Kcat);
    cudaEventRecord(eRk, st[1]);

    // st[2]: cache copies
    copy_cache<<<B_*PAST, 256, 0, st[2]>>>(kv_cache, ckv, Kcat, 0);
    copy_cache<<<B_*PAST, 256, 0, st[2]>>>(kr_cache, kr,  Kcat, 1024);
    cudaEventRecord(eCc, st[2]);

    // main: c -> LN -> qpre -> rope_q (critical path)
    cudaStreamWaitEvent(0, eW, 0);
    hgemm<false><<<PG, GEMM_THREADS, GEMM_SMEM>>>(
        xh, wdkvh, c, 8192, 1024, 1024, 0, 0, 0, 1024, 1024, 1024, 0, 1);
    layernorm_kernel<<<B_*SEQ, 256>>>(c, ckv, Kcat, ln_g, ln_b);
    cudaEventRecord(eLN, 0);
    hgemm<false><<<PG, GEMM_THREADS, GEMM_SMEM>>>(
        Kcat + (size_t)PAST * 2048, wqrh, qpre, 2048, 1024, 1024,
        SL2, 0, sE, 2048, 1024, 1024, 0, 4);
    rope_q_kernel<<<B_*SEQ, 512>>>(qpre, Qcat, bqr);

    // st[2]: valueT — overlaps scores+softmax
    cudaStreamWaitEvent(st[2], eLN, 0);
    cudaStreamWaitEvent(st[2], eT, 0);
    hgemm<true><<<PG, GEMM_THREADS, GEMM_SMEM, st[2]>>>(
        wuvTh, Kcat, vTh, 1024, 4096, 1024, 0, SL2, ES, 1024, 2048, 4096, 0, 4);
    cudaEventRecord(eV, st[2]);

    // ---------------- JOIN for scores ----------------
    cudaStreamWaitEvent(0, eXa, 0);
    cudaStreamWaitEvent(0, eRk, 0);
    cudaStreamWaitEvent(0, eCc, 0);

    // scores = Qcat @ Kcat^T (pre-scaled; K=2048; causal tile skip)
    hgemm<false><<<PG, GEMM_THREADS, GEMM_SMEM>>>(
        Qcat, Kcat, sc, 2048, 4096, 2048, sL2, SL2, sS, 2048, 2048, 4096, 1, 4);

    softmax_kernel<<<B_*SEQ, 256>>>(sc, wh);

    // att = w @ valueT^T (causal K-limit)
    cudaStreamWaitEvent(0, eV, 0);
    hgemm<true><<<PG, GEMM_THREADS, GEMM_SMEM>>>(
        wh, vTh, atth, 2048, 1024, 4096, sS, ES, sE, 4096, 4096, 1024, 2, 4);

    // out = att @ Wo^T
    hgemm<false><<<PG, GEMM_THREADS, GEMM_SMEM>>>(
        atth, woh, out, 8192, 1024, 1024, 0, 0, 0, 1024, 1024, 1024, 0, 1);
}

// round 13
// speedup vs baseline: 1.0130x; 1.0130x over previous
#include <cuda_runtime.h>
#include <cuda_fp16.h>
#include <math.h>
#include <stdint.h>

// ---------------- fixed problem shapes ----------------
#define B_    4
#define SEQ   2048
#define PAST  2048
#define EDIM  1024
#define LDIM  1024
#define STOT  4096
#define QSCALE 0.022097086912079608f   // 1/sqrt(2*LDIM)

// ---------------- scratch (device globals) ----------------
__device__ __align__(256) __half g_xh   [(size_t)B_*SEQ*EDIM];
__device__ __align__(256) __half g_Wqh  [EDIM*EDIM];
__device__ __align__(256) __half g_Wukh [LDIM*EDIM];
__device__ __align__(256) __half g_Wdkvh[LDIM*EDIM];
__device__ __align__(256) __half g_Wkrh [LDIM*EDIM];
__device__ __align__(256) __half g_Wqrh [EDIM*LDIM];
__device__ __align__(256) __half g_Woh  [EDIM*EDIM];
__device__ __align__(256) __half g_WuvTh[EDIM*LDIM];
__device__ __align__(256) __half g_absTh[LDIM*EDIM];
__device__ __align__(256) float  g_c    [(size_t)B_*SEQ*LDIM];
__device__ __align__(256) float  g_krp  [(size_t)B_*SEQ*LDIM];
__device__ __align__(256) float  g_qpre [(size_t)B_*SEQ*EDIM];
__device__ __align__(256) __half g_Kcat [(size_t)B_*STOT*2048];   // [ckv | kr] fp16
__device__ __align__(256) __half g_Qcat [(size_t)B_*SEQ*2048];    // [xa | q_r] fp16
__device__ __align__(256) float  g_sc   [(size_t)B_*SEQ*STOT];
__device__ __align__(256) __half g_wh   [(size_t)B_*SEQ*STOT];
__device__ __align__(256) __half g_vTh  [(size_t)B_*EDIM*STOT];   // value^T per batch [E,S]
__device__ __align__(256) __half g_atth [(size_t)B_*SEQ*EDIM];

// ================= GEMM config =================
// Persistent warp-specialized cg2 GEMM. Pair computes M=256 x N=256 tiles,
// double-buffered TMEM accumulators (cols 0-255 / 256-511).
// BK=128: per CTA per stage = A half (2x SW128 K64 blocks, 32KB) + B half (32KB).
#define BK 128
#define NSTG 3
#define STAGE_BYTES 65536
#define GEMM_THREADS 416            // 8 producer + 1 mma/fwd + 4 epilogue warps
#define GEMM_SMEM (NSTG*STAGE_BYTES + 1024 + 128)
#define GEMM_GRID 148               // 74 persistent cluster pairs

// arch-specific feature gate: tcgen05 needs sm_103a / sm_100a compilation
#if defined(__CUDA_ARCH__) && (defined(__CUDA_ARCH_FEAT_SM103_ALL) || defined(__CUDA_ARCH_FEAT_SM100_ALL) || defined(__CUDA_ARCH_FEAT_SM101_ALL))
#define USE_TCGEN05 1
#else
#define USE_TCGEN05 0
#endif

__device__ __forceinline__ void cp_async16(uint32_t dst, const void* src) {
    asm volatile("cp.async.cg.shared.global [%0], [%1], 16;" :: "r"(dst), "l"(src) : "memory");
}

#if USE_TCGEN05
__device__ __forceinline__ uint32_t sw128(uint32_t o) { return o ^ ((o >> 3) & 0x70u); }

__device__ __forceinline__ uint64_t make_desc(uint32_t addr) {
    return ((uint64_t)2 << 61) | (1ull << 46) | (64ull << 32) | (1ull << 16)
         | ((addr >> 4) & 0x3FFFull);
}

__device__ __forceinline__ bool elect_one() {
    uint32_t pred;
    asm volatile("{\n\t.reg .pred p;\n\telect.sync _|p, 0xFFFFFFFF;\n\tselp.b32 %0, 1, 0, p;\n\t}"
                 : "=r"(pred));
    return pred != 0;
}

__device__ __forceinline__ void mbar_init(uint32_t a, uint32_t cnt) {
    asm volatile("mbarrier.init.shared.b64 [%0], %1;" :: "r"(a), "r"(cnt) : "memory");
}

__device__ __forceinline__ void mbar_wait(uint32_t a, uint32_t ph) {
    asm volatile(
        "{\n\t.reg .pred P;\n"
        "LW%=:\n\t"
        "mbarrier.try_wait.parity.acquire.cta.shared::cta.b64 P, [%0], %1, 0x989680;\n\t"
        "@!P bra LW%=;\n\t}"
        :: "r"(a), "r"(ph) : "memory");
}

__device__ __forceinline__ void cp_async_arrive(uint32_t bar) {
    asm volatile("cp.async.mbarrier.arrive.noinc.shared::cta.b64 [%0];" :: "r"(bar) : "memory");
}

// arrive on leader (rank 0) CTA's mbarrier at the same smem offset
__device__ __forceinline__ void mbar_arrive_leader(uint32_t local_addr) {
    asm volatile(
        "{\n\t.reg .b32 remAddr;\n\t"
        "mapa.shared::cluster.u32 remAddr, %0, 0;\n\t"
        "mbarrier.arrive.shared::cluster.b64 _, [remAddr];\n\t}"
        :: "r"(local_addr) : "memory");
}

__device__ __forceinline__ void mma_f16_cg2(uint32_t d, uint64_t ad, uint64_t bd,
                                            uint32_t idesc, uint32_t en) {
    asm volatile(
        "{\n\t.reg .pred p;\n\tsetp.ne.u32 p, %4, 0;\n\t"
        "tcgen05.mma.cta_group::2.kind::f16 [%0], %1, %2, %3, "
        "{%5, %5, %5, %5, %5, %5, %5, %5}, p;\n\t}"
        :: "r"(d), "l"(ad), "l"(bd), "r"(idesc), "r"(en), "r"(0u) : "memory");
}

__device__ __forceinline__ void tc_commit_mc2(uint32_t bar) {
    asm volatile(
        "tcgen05.commit.cta_group::2.mbarrier::arrive::one.shared::cluster.multicast::cluster.b64 [%0], %1;"
        :: "r"(bar), "h"((uint16_t)3) : "memory");
}

__device__ __forceinline__ void ldtm32(uint32_t* r, uint32_t addr) {
    asm volatile(
        "tcgen05.ld.sync.aligned.32x32b.x32.b32 "
        "{%0, %1, %2, %3, %4, %5, %6, %7, "
        " %8, %9, %10, %11, %12, %13, %14, %15, "
        " %16, %17, %18, %19, %20, %21, %22, %23, "
        " %24, %25, %26, %27, %28, %29, %30, %31}, [%32];"
        : "=r"(r[0]),  "=r"(r[1]),  "=r"(r[2]),  "=r"(r[3]),
          "=r"(r[4]),  "=r"(r[5]),  "=r"(r[6]),  "=r"(r[7]),
          "=r"(r[8]),  "=r"(r[9]),  "=r"(r[10]), "=r"(r[11]),
          "=r"(r[12]), "=r"(r[13]), "=r"(r[14]), "=r"(r[15]),
          "=r"(r[16]), "=r"(r[17]), "=r"(r[18]), "=r"(r[19]),
          "=r"(r[20]), "=r"(r[21]), "=r"(r[22]), "=r"(r[23]),
          "=r"(r[24]), "=r"(r[25]), "=r"(r[26]), "=r"(r[27]),
          "=r"(r[28]), "=r"(r[29]), "=r"(r[30]), "=r"(r[31])
        : "r"(addr));
}
#endif  // USE_TCGEN05

// Persistent GEMM: C[z][M,N] = A[z][M,K] * B[z][N,K]^T, fp16 in, fp32 accum.
// M%256==0, N%256==0, K%128==0. Grid = GEMM_GRID CTAs (74 cg2 pairs), each pair
// strides over Z*(M/256)*(N/256) tiles. cflag bit0: causal tile skip;
// bit1: causal K-limit.
template<bool OUT_HALF>
__global__ void __launch_bounds__(GEMM_THREADS, 1) __cluster_dims__(2, 1, 1)
hgemm(const __half* __restrict__ A, const __half* __restrict__ Bm, void* __restrict__ Cv,
      int M, int N, int K, long long sA, long long sB, long long sC,
      int lda, int ldb, int ldc, int cflag, int Z)
{
    extern __shared__ char dynsmem[];
    const int tid  = threadIdx.x;
    const int wid  = tid >> 5;
    const int rank = blockIdx.x & 1;
    const int pairId = blockIdx.x >> 1;
    const int nPairs = gridDim.x >> 1;
    const int nN = N >> 8;
    const int tilesPerZ = (M >> 8) * nN;
    const int totalTiles = Z * tilesPerZ;

#if USE_TCGEN05
    uint32_t raw  = (uint32_t)__cvta_generic_to_shared(dynsmem);
    uint32_t tb   = (raw + 1023u) & ~1023u;
    uint32_t ctrl = tb + NSTG * STAGE_BYTES;
    // ctrl+0 tmem; full[s]=ctrl+8+8s; empty[s]=ctrl+40+8s; done[b]=ctrl+72+8b; free[b]=ctrl+88+8b

    if (tid == 0) {
        #pragma unroll
        for (int s = 0; s < NSTG; s++) {
            mbar_init(ctrl + 8  + 8*s, (rank == 0) ? 257u : 256u);
            mbar_init(ctrl + 40 + 8*s, 1);
        }
        mbar_init(ctrl + 72, 1); mbar_init(ctrl + 80, 1);
        mbar_init(ctrl + 88, 8); mbar_init(ctrl + 96, 8);
    }
    __syncthreads();
    if (wid == 8) {
        asm volatile("tcgen05.alloc.cta_group::2.sync.aligned.shared::cta.b32 [%0], %1;"
                     :: "r"(ctrl), "r"(512u) : "memory");
        asm volatile("tcgen05.relinquish_alloc_permit.cta_group::2.sync.aligned;");
    }
    __syncthreads();
    asm volatile("barrier.cluster.arrive.aligned;" ::: "memory");
    asm volatile("barrier.cluster.wait.aligned;"   ::: "memory");

    uint32_t tmem;
    asm volatile("ld.shared.b32 %0, [%1];" : "=r"(tmem) : "r"(ctrl));

    if (wid < 8) {
        // ================= producers: continuous cp.async stream =================
        // stage layout: [A k64-blk0 16K][A k64-blk1 16K][B blk0 16K][B blk1 16K]
        const int r0  = tid >> 3;
        const int c16 = tid & 7;
        uint32_t sw[4];
        #pragma unroll
        for (int i = 0; i < 4; i++) sw[i] = sw128((uint32_t)((r0 + 32*i) * 128 + c16 * 16));
        const long long la32 = (long long)lda * 32, lb32 = (long long)ldb * 32;

        int s = 0; uint32_t phE = 1;
        for (int t = pairId; t < totalTiles; t += nPairs) {
            const int z = t / tilesPerZ, r = t - z * tilesPerZ;
            const int m0 = (r / nN) << 8, n0 = (r % nN) << 8;
            if ((cflag & 1) && n0 >= m0 + 256 + PAST) continue;
            int nCh = K >> 7;
            if (cflag & 2) { int lim = (m0 + 256 + PAST) >> 7; if (lim < nCh) nCh = lim; }
            const __half* ap = A  + z * sA + (long long)(m0 + rank*128 + r0) * lda + c16 * 8;
            const __half* bp = Bm + z * sB + (long long)(n0 + rank*128 + r0) * ldb + c16 * 8;
            for (int kc = 0; kc < nCh; kc++) {
                mbar_wait(ctrl + 40 + 8*s, phE);
                uint32_t sb = tb + s * STAGE_BYTES;
                #pragma unroll
                for (int b = 0; b < 2; b++) {
                    #pragma unroll
                    for (int i = 0; i < 4; i++)
                        cp_async16(sb + b*16384u + sw[i], ap + b*64 + i * la32);
                    #pragma unroll
                    for (int i = 0; i < 4; i++)
                        cp_async16(sb + 32768u + b*16384u + sw[i], bp + b*64 + i * lb32);
                }
                cp_async_arrive(ctrl + 8 + 8*s);
                ap += BK; bp += BK;
                if (++s == NSTG) { s = 0; phE ^= 1; }
            }
        }
    } else if (wid == 8 && rank == 0) {
        // ================= leader MMA warp =================
        const uint32_t idesc = (1u << 4) | (32u << 17) | (16u << 24);
        int s = 0; uint32_t phF = 0;
        uint32_t phFree0 = 1, phFree1 = 1;
        int tc = 0;
        for (int t = pairId; t < totalTiles; t += nPairs) {
            const int z = t / tilesPerZ, r = t - z * tilesPerZ;
            const int m0 = (r / nN) << 8, n0 = (r % nN) << 8;
            if ((cflag & 1) && n0 >= m0 + 256 + PAST) continue;
            int nCh = K >> 7;
            if (cflag & 2) { int lim = (m0 + 256 + PAST) >> 7; if (lim < nCh) nCh = lim; }
            const int buf = tc & 1;
            if (buf == 0) { mbar_wait(ctrl + 88, phFree0); phFree0 ^= 1; }
            else          { mbar_wait(ctrl + 96, phFree1); phFree1 ^= 1; }
            const uint32_t dtm = tmem + buf * 256u;
            for (int kc = 0; kc < nCh; kc++) {
                mbar_wait(ctrl + 8 + 8*s, phF);
                if (elect_one()) {
                    asm volatile("fence.proxy.async.shared::cta;" ::: "memory");
                    #pragma unroll
                    for (int st = 0; st < 8; st++) {
                        uint64_t ad = make_desc(tb + s * STAGE_BYTES + (st >> 2) * 16384u)
                                    + (st & 3) * 2;
                        uint64_t bd = make_desc(tb + s * STAGE_BYTES + 32768u + (st >> 2) * 16384u)
                                    + (st & 3) * 2;
                        mma_f16_cg2(dtm, ad, bd, idesc, (kc == 0 && st == 0) ? 0u : 1u);
                    }
                    tc_commit_mc2(ctrl + 40 + 8*s);
                }
                if (++s == NSTG) { s = 0; phF ^= 1; }
            }
            if (elect_one()) tc_commit_mc2(ctrl + 72 + 8*buf);   // done[buf] -> both CTAs
            tc++;
        }
    } else if (wid == 8) {
        // ================= follower forward warp =================
        int s = 0; uint32_t phF = 0;
        for (int t = pairId; t < totalTiles; t += nPairs) {
            const int z = t / tilesPerZ, r = t - z * tilesPerZ;
            const int m0 = (r / nN) << 8, n0 = (r % nN) << 8;
            if ((cflag & 1) && n0 >= m0 + 256 + PAST) continue;
            int nCh = K >> 7;
            if (cflag & 2) { int lim = (m0 + 256 + PAST) >> 7; if (lim < nCh) nCh = lim; }
            for (int kc = 0; kc < nCh; kc++) {
                mbar_wait(ctrl + 8 + 8*s, phF);
                if (elect_one()) mbar_arrive_leader(ctrl + 8 + 8*s);
                if (++s == NSTG) { s = 0; phF ^= 1; }
            }
        }
    } else {
        // ================= epilogue warps (wid 9..12) =================
        // TMEM lane subpartition is wid % 4 (HW-fixed): row group = wid & 3.
        const int we = wid & 3;
        const int l = tid & 31;
        uint32_t phD0 = 0, phD1 = 0;
        int tc = 0;
        for (int t = pairId; t < totalTiles; t += nPairs) {
            const int z = t / tilesPerZ, r = t - z * tilesPerZ;
            const int m0 = (r / nN) << 8, n0 = (r % nN) << 8;
            if ((cflag & 1) && n0 >= m0 + 256 + PAST) continue;
            const int buf = tc & 1;
            if (buf == 0) { mbar_wait(ctrl + 72, phD0); phD0 ^= 1; }
            else          { mbar_wait(ctrl + 80, phD1); phD1 ^= 1; }
            asm volatile("tcgen05.fence::after_thread_sync;" ::: "memory");
            const uint32_t dtm = tmem + buf * 256u;
            const long long row = (long long)m0 + rank * 128 + we * 32 + l;
            if (OUT_HALF) {
                __half* C = (__half*)Cv + z * sC + row * ldc + n0;
                for (int b8 = 0; b8 < 8; b8++) {
                    uint32_t rg[32];
                    ldtm32(rg, dtm + b8 * 32);
                    asm volatile("tcgen05.wait::ld.sync.aligned;" ::: "memory");
                    uint32_t h[16];
                    #pragma unroll
                    for (int j = 0; j < 16; j++) {
                        __half2 hv = __floats2half2_rn(__uint_as_float(rg[2*j]), __uint_as_float(rg[2*j+1]));
                        h[j] = *reinterpret_cast<uint32_t*>(&hv);
                    }
                    uint4* dst = (uint4*)(C + b8 * 32);
                    #pragma unroll
                    for (int q = 0; q < 4; q++) dst[q] = make_uint4(h[4*q], h[4*q+1], h[4*q+2], h[4*q+3]);
                }
            } else {
                float* C = (float*)Cv + z * sC + row * ldc + n0;
                for (int b8 = 0; b8 < 8; b8++) {
                    uint32_t rg[32];
                    ldtm32(rg, dtm + b8 * 32);
                    asm volatile("tcgen05.wait::ld.sync.aligned;" ::: "memory");
                    float4* dst = (float4*)(C + b8 * 32);
                    #pragma unroll
                    for (int q = 0; q < 8; q++)
                        dst[q] = make_float4(__uint_as_float(rg[4*q]),   __uint_as_float(rg[4*q+1]),
                                             __uint_as_float(rg[4*q+2]), __uint_as_float(rg[4*q+3]));
                }
            }
            asm volatile("tcgen05.fence::before_thread_sync;" ::: "memory");
            if (elect_one()) {
                if (rank == 0)
                    asm volatile("mbarrier.arrive.shared.b64 _, [%0];" :: "r"(ctrl + 88 + 8*buf) : "memory");
                else
                    mbar_arrive_leader(ctrl + 88 + 8*buf);
            }
            tc++;
        }
    }

    __syncthreads();
    if (wid == 8)
        asm volatile("tcgen05.dealloc.cta_group::2.sync.aligned.b32 %0, %1;" :: "r"(tmem), "r"(512u));
    asm volatile("barrier.cluster.arrive.aligned;" ::: "memory");
    asm volatile("barrier.cluster.wait.aligned;"   ::: "memory");

#else
    // ===================== mma.sync fallback (plain sm_103), persistent, K64 steps =====================
    const int lane = tid & 31;
    const int g  = lane >> 2;
    const int tg = lane & 3;
    uint32_t sbase = (uint32_t)__cvta_generic_to_shared(dynsmem);
    sbase = (sbase + 127u) & ~127u;
    const uint32_t ST_A = 0, ST_B = 128 * 144, ST_SZ = 128 * 144 + 256 * 144;

    for (int t = pairId; t < totalTiles; t += nPairs) {
        const int z = t / tilesPerZ, r = t - z * tilesPerZ;
        const int m0 = (r / nN) << 8, n0 = (r % nN) << 8;
        if ((cflag & 1) && n0 >= m0 + 256 + PAST) continue;
        int nCh = K >> 6;
        if (cflag & 2) { int lim = (m0 + 256 + PAST) >> 6; if (lim < nCh) nCh = lim; }
        const __half* At = A  + z * sA;
        const __half* Bt = Bm + z * sB;
        const int m0h = m0 + rank * 128;

        auto load_stage = [&](int s, int kk) {
            uint32_t sb = sbase + (uint32_t)s * ST_SZ;
            for (int idx = tid; idx < 3072; idx += GEMM_THREADS) {
                if (idx < 1024) {
                    int row = idx >> 3, c = idx & 7;
                    cp_async16(sb + ST_A + row * 144 + c * 16,
                               At + (long long)(m0h + row) * lda + kk + c * 8);
                } else {
                    int j = idx - 1024;
                    int row = j >> 3, c = j & 7;
                    cp_async16(sb + ST_B + row * 144 + c * 16,
                               Bt + (long long)(n0 + row) * ldb + kk + c * 8);
                }
            }
            asm volatile("cp.async.commit_group;" ::: "memory");
        };

        const int wm = (wid >> 1) * 32;
        const int wn = (wid & 1) * 128;

        float acc[16][4];
        #pragma unroll
        for (int jn = 0; jn < 16; jn++)
            #pragma unroll
            for (int q = 0; q < 4; q++) acc[jn][q] = 0.f;

        load_stage(0, 0);
        for (int kc = 0; kc < nCh; kc++) {
            if (kc + 1 < nCh) {
                load_stage((kc + 1) & 1, (kc + 1) * 64);
                asm volatile("cp.async.wait_group 1;" ::: "memory");
            } else {
                asm volatile("cp.async.wait_group 0;" ::: "memory");
            }
            __syncthreads();

            if (wid < 8) {
                uint32_t sb = sbase + (uint32_t)(kc & 1) * ST_SZ;
                #pragma unroll
                for (int k0 = 0; k0 < 64; k0 += 16) {
                    uint32_t a[2][2];
                    {
                        uint32_t r0a = sb + ST_A + (uint32_t)(wm + g) * 144 + (uint32_t)(k0 + tg * 2) * 2;
                        asm volatile("ld.shared.b32 %0, [%1];"        : "=r"(a[0][0]) : "r"(r0a));
                        asm volatile("ld.shared.b32 %0, [%1 + 1152];" : "=r"(a[0][1]) : "r"(r0a));
                        asm volatile("ld.shared.b32 %0, [%1 + 16];"   : "=r"(a[1][0]) : "r"(r0a));
                        asm volatile("ld.shared.b32 %0, [%1 + 1168];" : "=r"(a[1][1]) : "r"(r0a));
                    }
                    #pragma unroll
                    for (int jn = 0; jn < 16; jn++) {
                        uint32_t b0, b1;
                        uint32_t rb = sb + ST_B + (uint32_t)(wn + jn * 8 + g) * 144 + (uint32_t)(k0 + tg * 2) * 2;
                        asm volatile("ld.shared.b32 %0, [%1];"      : "=r"(b0) : "r"(rb));
                        asm volatile("ld.shared.b32 %0, [%1 + 16];" : "=r"(b1) : "r"(rb));
                        asm volatile(
                            "mma.sync.aligned.m16n8k16.row.col.f32.f16.f16.f32 "
                            "{%0,%1,%2,%3}, {%4,%5,%6,%7}, {%8,%9}, {%0,%1,%2,%3};"
                            : "+f"(acc[jn][0]), "+f"(acc[jn][1]),
                              "+f"(acc[jn][2]), "+f"(acc[jn][3])
                            : "r"(a[0][0]), "r"(a[0][1]), "r"(a[1][0]), "r"(a[1][1]),
                              "r"(b0), "r"(b1));
                    }
                }
            }
            __syncthreads();
        }

        if (wid < 8) {
            const long long r0w = (long long)m0h + wm + g;
            #pragma unroll
            for (int jn = 0; jn < 16; jn++) {
                const long long cc = (long long)n0 + wn + jn * 8 + tg * 2;
                if (OUT_HALF) {
                    __half* C = (__half*)Cv + z * sC;
                    *(__half2*)(C + r0w * ldc + cc)       = __floats2half2_rn(acc[jn][0], acc[jn][1]);
                    *(__half2*)(C + (r0w + 8) * ldc + cc) = __floats2half2_rn(acc[jn][2], acc[jn][3]);
                } else {
                    float* C = (float*)Cv + z * sC;
                    float* p0 = C + r0w * ldc + cc;
                    float* p1 = C + (r0w + 8) * ldc + cc;
                    p0[0] = acc[jn][0]; p0[1] = acc[jn][1];
                    p1[0] = acc[jn][2]; p1[1] = acc[jn][3];
                }
            }
        }
        __syncthreads();
    }
#endif
}

// ================= elementwise kernels =================
__device__ __forceinline__ uint32_t h2bits(__half2 h) { return *reinterpret_cast<uint32_t*>(&h); }

__global__ void cvt_f32_f16(const float* __restrict__ in, __half* __restrict__ out, int n8) {
    int i = blockIdx.x * 256 + threadIdx.x;
    if (i < n8) {
        float4 a = ((const float4*)in)[2*i], b = ((const float4*)in)[2*i+1];
        uint4 o;
        o.x = h2bits(__floats2half2_rn(a.x, a.y));
        o.y = h2bits(__floats2half2_rn(a.z, a.w));
        o.z = h2bits(__floats2half2_rn(b.x, b.y));
        o.w = h2bits(__floats2half2_rn(b.z, b.w));
        ((uint4*)out)[i] = o;
    }
}

__global__ void cvt_weights6(const float* s0, const float* s1, const float* s2,
                             const float* s3, const float* s4, const float* s5,
                             __half* d0, __half* d1, __half* d2,
                             __half* d3, __half* d4, __half* d5) {
    int i = blockIdx.x * 256 + threadIdx.x;
    int w = i >> 17;
    int j = i & 131071;
    const float* s; __half* d;
    switch (w) {
        case 0: s = s0; d = d0; break;
        case 1: s = s1; d = d1; break;
        case 2: s = s2; d = d2; break;
        case 3: s = s3; d = d3; break;
        case 4: s = s4; d = d4; break;
        default: s = s5; d = d5; break;
    }
    const float sc = (w == 1 || w == 4) ? QSCALE : 1.0f;
    float4 a = ((const float4*)s)[2*j], b = ((const float4*)s)[2*j+1];
    uint4 o;
    o.x = h2bits(__floats2half2_rn(a.x * sc, a.y * sc));
    o.y = h2bits(__floats2half2_rn(a.z * sc, a.w * sc));
    o.z = h2bits(__floats2half2_rn(b.x * sc, b.y * sc));
    o.w = h2bits(__floats2half2_rn(b.z * sc, b.w * sc));
    ((uint4*)d)[j] = o;
}

__global__ void transpose_f32_f16(const float* __restrict__ in, __half* __restrict__ out, int R, int C) {
    __shared__ float t[32][33];
    int bx = blockIdx.x * 32, by = blockIdx.y * 32;
    #pragma unroll
    for (int j = 0; j < 32; j += 8)
        t[threadIdx.y + j][threadIdx.x] = in[(long long)(by + threadIdx.y + j) * C + bx + threadIdx.x];
    __syncthreads();
    #pragma unroll
    for (int j = 0; j < 32; j += 8)
        out[(long long)(bx + threadIdx.y + j) * R + by + threadIdx.x] =
            __float2half_rn(t[threadIdx.x][threadIdx.y + j]);
}

__global__ void copy_cache(const float* __restrict__ src, float* __restrict__ dstF,
                           __half* __restrict__ dstH, int hcol) {
    int row = blockIdx.x; int b = row / PAST, r = row % PAST;
    const float4* s  = (const float4*)(src + (size_t)row * 1024);
    float4* dF = (float4*)(dstF + ((size_t)b * STOT + r) * 1024);
    __half* dH = dstH + ((size_t)b * STOT + r) * 2048 + hcol;
    int j = threadIdx.x;
    float4 v = s[j];
    dF[j] = v;
    uint2 u; u.x = h2bits(__floats2half2_rn(v.x, v.y)); u.y = h2bits(__floats2half2_rn(v.z, v.w));
    *(uint2*)(dH + j * 4) = u;
}

__device__ __forceinline__ float blk_sum(float v, float* red) {
    const int tid = threadIdx.x;
    #pragma unroll
    for (int o = 16; o > 0; o >>= 1) v += __shfl_xor_sync(0xffffffffu, v, o);
    if ((tid & 31) == 0) red[tid >> 5] = v;
    __syncthreads();
    float t = (tid < 8) ? red[tid] : 0.f;
    if (tid < 32) {
        #pragma unroll
        for (int o = 4; o > 0; o >>= 1) t += __shfl_xor_sync(0xffffffffu, t, o);
        if (tid == 0) red[0] = t;
    }
    __syncthreads();
    float r = red[0];
    __syncthreads();
    return r;
}

__device__ __forceinline__ float blk_max(float v, float* red) {
    const int tid = threadIdx.x;
    #pragma unroll
    for (int o = 16; o > 0; o >>= 1) v = fmaxf(v, __shfl_xor_sync(0xffffffffu, v, o));
    if ((tid & 31) == 0) red[tid >> 5] = v;
    __syncthreads();
    float t = (tid < 8) ? red[tid] : -3.4e38f;
    if (tid < 32) {
        #pragma unroll
        for (int o = 4; o > 0; o >>= 1) t = fmaxf(t, __shfl_xor_sync(0xffffffffu, t, o));
        if (tid == 0) red[0] = t;
    }
    __syncthreads();
    float r = red[0];
    __syncthreads();
    return r;
}

__global__ void layernorm_kernel(const float* __restrict__ c, float* __restrict__ ckv,
                                 __half* __restrict__ kcat,
                                 const float* __restrict__ g, const float* __restrict__ b) {
    const int row = blockIdx.x; const int bb = row / SEQ, si = row % SEQ;
    const float* p = c + (size_t)row * LDIM;
    float*  o  = ckv  + ((size_t)bb * STOT + PAST + si) * 1024;
    __half* oh = kcat + ((size_t)bb * STOT + PAST + si) * 2048;
    __shared__ float red[8];
    const int tid = threadIdx.x;
    float s = 0.f, s2 = 0.f;
    for (int j = tid; j < LDIM; j += 256) { float v = p[j]; s += v; s2 += v * v; }
    s  = blk_sum(s,  red);
    s2 = blk_sum(s2, red);
    const float mean = s * (1.f / LDIM);
    const float var  = fmaxf(s2 * (1.f / LDIM) - mean * mean, 0.f);
    const float inv  = rsqrtf(var + 1e-5f);
    for (int j = tid; j < LDIM; j += 256) {
        float v = (p[j] - mean) * inv * g[j] + b[j];
        o[j] = v; oh[j] = __float2half_rn(v);
    }
}

__global__ void rope_k_kernel(const float* __restrict__ in, float* __restrict__ kr,
                              __half* __restrict__ kcat) {
    const int row = blockIdx.x; const int bb = row / SEQ, t = row % SEQ;
    const int j = threadIdx.x;
    const float* pi = in + (size_t)row * 1024;
    float*  po = kr   + ((size_t)bb * STOT + PAST + t) * 1024;
    __half* ph = kcat + ((size_t)bb * STOT + PAST + t) * 2048 + 1024;
    float x1 = pi[j], x2 = pi[j + 512];
    const float inv_freq = powf(10000.f, -(float)(2 * j) * (1.f / 1024.f));
    float sn, cs; sincosf((float)t * inv_freq, &sn, &cs);
    float y1 = x1 * cs - x2 * sn, y2 = x2 * cs + x1 * sn;
    po[j] = y1; po[j + 512] = y2;
    ph[j] = __float2half_rn(y1); ph[j + 512] = __float2half_rn(y2);
}

__global__ void rope_q_kernel(const float* __restrict__ in, __half* __restrict__ qcat,
                              const float* __restrict__ bias) {
    const int row = blockIdx.x; const int t = row % SEQ;
    const int j = threadIdx.x;
    const float* pi = in + (size_t)row * 1024;
    __half* ph = qcat + (size_t)row * 2048 + 1024;
    float x1 = pi[j] + QSCALE * bias[j], x2 = pi[j + 512] + QSCALE * bias[j + 512];
    const float inv_freq = powf(10000.f, -(float)(2 * j) * (1.f / 1024.f));
    float sn, cs; sincosf((float)t * inv_freq, &sn, &cs);
    ph[j]       = __float2half_rn(x1 * cs - x2 * sn);
    ph[j + 512] = __float2half_rn(x2 * cs + x1 * sn);
}

__global__ void softmax_kernel(const float* __restrict__ sc, __half* __restrict__ wh) {
    const int row = blockIdx.x;
    const int si  = row % SEQ;
    const int valid = si + PAST + 1;
    const float* p = sc + (size_t)row * STOT;
    __half* o = wh + (size_t)row * STOT;
    __shared__ float buf[STOT];
    __shared__ float red[8];
    const int tid = threadIdx.x;

    float mx = -3.4e38f;
    for (int j = tid; j < valid; j += 256) { float v = p[j]; buf[j] = v; mx = fmaxf(mx, v); }
    mx = blk_max(mx, red);
    float sum = 0.f;
    for (int j = tid; j < valid; j += 256) { float e = __expf(buf[j] - mx); buf[j] = e; sum += e; }
    sum = blk_sum(sum, red);
    const float inv = 1.f / sum;
    for (int j = tid; j < valid; j += 256) o[j] = __float2half_rn(buf[j] * inv);
    for (int j = valid + tid; j < STOT; j += 256) o[j] = __float2half_rn(0.f);
}

// ================= launch =================
extern "C" void kernel_launch(void* const* d_in, const int* in_sizes, int n_in,
                              void* d_out, int out_size)
{
    (void)in_sizes; (void)n_in; (void)out_size;
    const float* x        = (const float*)d_in[0];
    const float* kv_cache = (const float*)d_in[1];
    const float* kr_cache = (const float*)d_in[2];
    const float* Wq       = (const float*)d_in[3];
    const float* Wdkv     = (const float*)d_in[4];
    const float* Wuk      = (const float*)d_in[5];
    const float* Wuv      = (const float*)d_in[6];
    const float* Wo       = (const float*)d_in[7];
    const float* Wkr      = (const float*)d_in[8];
    const float* Wqr      = (const float*)d_in[9];
    const float* bqr      = (const float*)d_in[10];
    const float* ln_g     = (const float*)d_in[11];
    const float* ln_b     = (const float*)d_in[12];

    float* out = (float*)d_out;
    float* ckv = out + (size_t)B_ * SEQ * EDIM;
    float* kr  = ckv + (size_t)B_ * STOT * LDIM;

    __half *xh, *wqh, *wukh, *wdkvh, *wkrh, *wqrh, *woh, *wuvTh, *absTh, *Kcat, *Qcat, *wh, *vTh, *atth;
    float *c, *krp, *qpre, *sc;
    cudaGetSymbolAddress((void**)&xh,    g_xh);
    cudaGetSymbolAddress((void**)&wqh,   g_Wqh);
    cudaGetSymbolAddress((void**)&wukh,  g_Wukh);
    cudaGetSymbolAddress((void**)&wdkvh, g_Wdkvh);
    cudaGetSymbolAddress((void**)&wkrh,  g_Wkrh);
    cudaGetSymbolAddress((void**)&wqrh,  g_Wqrh);
    cudaGetSymbolAddress((void**)&woh,   g_Woh);
    cudaGetSymbolAddress((void**)&wuvTh, g_WuvTh);
    cudaGetSymbolAddress((void**)&absTh, g_absTh);
    cudaGetSymbolAddress((void**)&c,     g_c);
    cudaGetSymbolAddress((void**)&krp,   g_krp);
    cudaGetSymbolAddress((void**)&qpre,  g_qpre);
    cudaGetSymbolAddress((void**)&Kcat,  g_Kcat);
    cudaGetSymbolAddress((void**)&Qcat,  g_Qcat);
    cudaGetSymbolAddress((void**)&sc,    g_sc);
    cudaGetSymbolAddress((void**)&wh,    g_wh);
    cudaGetSymbolAddress((void**)&vTh,   g_vTh);
    cudaGetSymbolAddress((void**)&atth,  g_atth);

    cudaFuncSetAttribute(hgemm<false>, cudaFuncAttributeMaxDynamicSharedMemorySize, GEMM_SMEM);
    cudaFuncSetAttribute(hgemm<true>,  cudaFuncAttributeMaxDynamicSharedMemorySize, GEMM_SMEM);

    // ---- proven topology: 3 streams, 9 events, single-use ----
    static cudaStream_t st[3] = {nullptr, nullptr, nullptr};
    static cudaEvent_t  ev[10] = {};
    if (st[0] == nullptr) {
        for (int i = 0; i < 3; i++) cudaStreamCreateWithFlags(&st[i], cudaStreamNonBlocking);
        for (int i = 0; i < 10; i++) cudaEventCreateWithFlags(&ev[i], cudaEventDisableTiming);
    }
    cudaEvent_t eFork = ev[0], eX = ev[1], eW = ev[2], eXa = ev[3], eT = ev[4],
                eRk = ev[5], eCc = ev[6], eLN = ev[7], eV = ev[8];

    const long long sL2 = (long long)SEQ * 2048;
    const long long SL2 = (long long)STOT * 2048;
    const long long sS  = (long long)SEQ * STOT;
    const long long sE  = (long long)SEQ * 1024;
    const long long ES  = (long long)EDIM * STOT;
    const dim3 PG(GEMM_GRID, 1, 1);

    // ---------------- FORK ----------------
    cudaEventRecord(eFork, 0);
    for (int i = 0; i < 3; i++) cudaStreamWaitEvent(st[i], eFork, 0);

    cvt_f32_f16<<<4096, 256>>>(x, xh, (B_*SEQ*EDIM)/8);
    cudaEventRecord(eX, 0);

    // st[0]: weights cvt -> absT -> xa (Qcat left)
    cvt_weights6<<<3072, 256, 0, st[0]>>>(Wq, Wuk, Wdkv, Wkr, Wqr, Wo,
                                          wqh, wukh, wdkvh, wkrh, wqrh, woh);
    cudaEventRecord(eW, st[0]);
    hgemm<true><<<PG, GEMM_THREADS, GEMM_SMEM, st[0]>>>(
        wukh, wqh, absTh, 1024, 1024, 1024, 0, 0, 0, 1024, 1024, 1024, 0, 1);
    cudaStreamWaitEvent(st[0], eX, 0);
    hgemm<true><<<PG, GEMM_THREADS, GEMM_SMEM, st[0]>>>(
        xh, absTh, Qcat, 8192, 1024, 1024, 0, 0, 0, 1024, 1024, 2048, 0, 1);
    cudaEventRecord(eXa, st[0]);

    // st[1]: Wuv transpose, then krp -> rope_k
    transpose_f32_f16<<<dim3(32, 32), dim3(32, 8), 0, st[1]>>>(Wuv, wuvTh, LDIM, EDIM);
    cudaEventRecord(eT, st[1]);
    cudaStreamWaitEvent(st[1], eX, 0);
    cudaStreamWaitEvent(st[1], eW, 0);
    hgemm<false><<<PG, GEMM_THREADS, GEMM_SMEM, st[1]>>>(
        xh, wkrh, krp, 8192, 1024, 1024, 0, 0, 0, 1024, 1024, 1024, 0, 1);
    rope_k_kernel<<<B_*SEQ, 512, 0, st[1]>>>(krp, kr, Kcat);
    cudaEventRecord(eRk, st[1]);

    // st[2]: cache copies
    copy_cache<<<B_*PAST, 256, 0, st[2]>>>(kv_cache, ckv, Kcat, 0);
    copy_cache<<<B_*PAST, 256, 0, st[2]>>>(kr_cache, kr,  Kcat, 1024);
    cudaEventRecord(eCc, st[2]);

    // main: c -> LN -> qpre -> rope_q (critical path)
    cudaStreamWaitEvent(0, eW, 0);
    hgemm<false><<<PG, GEMM_THREADS, GEMM_SMEM>>>(
        xh, wdkvh, c, 8192, 1024, 1024, 0, 0, 0, 1024, 1024, 1024, 0, 1);
    layernorm_kernel<<<B_*SEQ, 256>>>(c, ckv, Kcat, ln_g, ln_b);
    cudaEventRecord(eLN, 0);
    hgemm<false><<<PG, GEMM_THREADS, GEMM_SMEM>>>(
        Kcat + (size_t)PAST * 2048, wqrh, qpre, 2048, 1024, 1024,
        SL2, 0, sE, 2048, 1024, 1024, 0, 4);
    rope_q_kernel<<<B_*SEQ, 512>>>(qpre, Qcat, bqr);

    // st[2]: valueT — overlaps scores+softmax
    cudaStreamWaitEvent(st[2], eLN, 0);
    cudaStreamWaitEvent(st[2], eT, 0);
    hgemm<true><<<PG, GEMM_THREADS, GEMM_SMEM, st[2]>>>(
        wuvTh, Kcat, vTh, 1024, 4096, 1024, 0, SL2, ES, 1024, 2048, 4096, 0, 4);
    cudaEventRecord(eV, st[2]);

    // ---------------- JOIN for scores ----------------
    cudaStreamWaitEvent(0, eXa, 0);
    cudaStreamWaitEvent(0, eRk, 0);
    cudaStreamWaitEvent(0, eCc, 0);

    // scores = Qcat @ Kcat^T (pre-scaled; K=2048; causal tile skip)
    hgemm<false><<<PG, GEMM_THREADS, GEMM_SMEM>>>(
        Qcat, Kcat, sc, 2048, 4096, 2048, sL2, SL2, sS, 2048, 2048, 4096, 1, 4);

    softmax_kernel<<<B_*SEQ, 256>>>(sc, wh);

    // att = w @ valueT^T (causal K-limit)
    cudaStreamWaitEvent(0, eV, 0);
    hgemm<true><<<PG, GEMM_THREADS, GEMM_SMEM>>>(
        wh, vTh, atth, 2048, 1024, 4096, sS, ES, sE, 4096, 4096, 1024, 2, 4);

    // out = att @ Wo^T
    hgemm<false><<<PG, GEMM_THREADS, GEMM_SMEM>>>(
        atth, woh, out, 8192, 1024, 1024, 0, 0, 0, 1024, 1024, 1024, 0, 1);
}

// round 14
// speedup vs baseline: 1.0462x; 1.0328x over previous
#include <cuda_runtime.h>
#include <cuda_fp16.h>
#include <math.h>
#include <stdint.h>

// ---------------- fixed problem shapes ----------------
#define B_    4
#define SEQ   2048
#define PAST  2048
#define EDIM  1024
#define LDIM  1024
#define STOT  4096
#define QSCALE 0.022097086912079608f   // 1/sqrt(2*LDIM)

// ---------------- scratch (device globals) ----------------
__device__ __align__(256) __half g_xh   [(size_t)B_*SEQ*EDIM];
__device__ __align__(256) __half g_Wqh  [EDIM*EDIM];
__device__ __align__(256) __half g_Wukh [LDIM*EDIM];
__device__ __align__(256) __half g_Wdkvh[LDIM*EDIM];
__device__ __align__(256) __half g_Wkrh [LDIM*EDIM];
__device__ __align__(256) __half g_Wqrh [EDIM*LDIM];
__device__ __align__(256) __half g_Woh  [EDIM*EDIM];
__device__ __align__(256) __half g_WuvTh[EDIM*LDIM];
__device__ __align__(256) __half g_absTh[LDIM*EDIM];
__device__ __align__(256) float  g_c    [(size_t)B_*SEQ*LDIM];
__device__ __align__(256) __half g_krp  [(size_t)B_*SEQ*LDIM];   // fp16 now
__device__ __align__(256) __half g_qpre [(size_t)B_*SEQ*EDIM];   // fp16 now
__device__ __align__(256) __half g_Kcat [(size_t)B_*STOT*2048];  // [ckv | kr] fp16
__device__ __align__(256) __half g_Qcat [(size_t)B_*SEQ*2048];   // [xa | q_r] fp16
__device__ __align__(256) float  g_sc   [(size_t)B_*SEQ*STOT];
__device__ __align__(256) __half g_wh   [(size_t)B_*SEQ*STOT];
__device__ __align__(256) __half g_vTh  [(size_t)B_*EDIM*STOT];  // value^T per batch [E,S]
__device__ __align__(256) __half g_atth [(size_t)B_*SEQ*EDIM];

// ================= GEMM config (R9 best: 418.8us) =================
// 2-CTA cooperative tile: pair computes M=256 x N=512. Per CTA per stage:
//   A half (128x64 fp16, 16KB) + B quarter0 (16KB) + B quarter1 (16KB)
#define BM 256
#define BN 512
#define BK 64
#define NSTG 4
#define STAGE_BYTES 49152
#define GEMM_THREADS 288            // 8 producer/epilogue warps + 1 control warp
#define GEMM_SMEM (NSTG*STAGE_BYTES + 1024 + 128)

// arch-specific feature gate: tcgen05 needs sm_103a / sm_100a compilation
#if defined(__CUDA_ARCH__) && (defined(__CUDA_ARCH_FEAT_SM103_ALL) || defined(__CUDA_ARCH_FEAT_SM100_ALL) || defined(__CUDA_ARCH_FEAT_SM101_ALL))
#define USE_TCGEN05 1
#else
#define USE_TCGEN05 0
#endif

__device__ __forceinline__ void cp_async16(uint32_t dst, const void* src) {
    asm volatile("cp.async.cg.shared.global [%0], [%1], 16;" :: "r"(dst), "l"(src) : "memory");
}

#if USE_TCGEN05
__device__ __forceinline__ uint32_t sw128(uint32_t o) { return o ^ ((o >> 3) & 0x70u); }

__device__ __forceinline__ uint64_t make_desc(uint32_t addr) {
    return ((uint64_t)2 << 61)      // SW128
         | (1ull << 46)             // Blackwell version
         | (64ull << 32)            // SBO = 64
         | (1ull  << 16)            // LBO = 1
         | ((addr >> 4) & 0x3FFFull);
}

__device__ __forceinline__ bool elect_one() {
    uint32_t pred;
    asm volatile("{\n\t.reg .pred p;\n\telect.sync _|p, 0xFFFFFFFF;\n\tselp.b32 %0, 1, 0, p;\n\t}"
                 : "=r"(pred));
    return pred != 0;
}

__device__ __forceinline__ void mbar_init(uint32_t a, uint32_t cnt) {
    asm volatile("mbarrier.init.shared.b64 [%0], %1;" :: "r"(a), "r"(cnt) : "memory");
}

__device__ __forceinline__ void mbar_wait(uint32_t a, uint32_t ph) {
    asm volatile(
        "{\n\t.reg .pred P;\n"
        "LW%=:\n\t"
        "mbarrier.try_wait.parity.acquire.cta.shared::cta.b64 P, [%0], %1, 0x989680;\n\t"
        "@!P bra LW%=;\n\t}"
        :: "r"(a), "r"(ph) : "memory");
}

__device__ __forceinline__ void cp_async_arrive(uint32_t bar) {
    asm volatile("cp.async.mbarrier.arrive.noinc.shared::cta.b64 [%0];" :: "r"(bar) : "memory");
}

// arrive on leader (rank 0) CTA's mbarrier at the same smem offset
__device__ __forceinline__ void mbar_arrive_leader(uint32_t local_addr) {
    asm volatile(
        "{\n\t.reg .b32 remAddr;\n\t"
        "mapa.shared::cluster.u32 remAddr, %0, 0;\n\t"
        "mbarrier.arrive.shared::cluster.b64 _, [remAddr];\n\t}"
        :: "r"(local_addr) : "memory");
}

__device__ __forceinline__ void mma_f16_cg2(uint32_t d, uint64_t ad, uint64_t bd,
                                            uint32_t idesc, uint32_t en) {
    asm volatile(
        "{\n\t.reg .pred p;\n\tsetp.ne.u32 p, %4, 0;\n\t"
        "tcgen05.mma.cta_group::2.kind::f16 [%0], %1, %2, %3, "
        "{%5, %5, %5, %5, %5, %5, %5, %5}, p;\n\t}"
        :: "r"(d), "l"(ad), "l"(bd), "r"(idesc), "r"(en), "r"(0u) : "memory");
}

__device__ __forceinline__ void tc_commit_mc2(uint32_t bar) {
    asm volatile(
        "tcgen05.commit.cta_group::2.mbarrier::arrive::one.shared::cluster.multicast::cluster.b64 [%0], %1;"
        :: "r"(bar), "h"((uint16_t)3) : "memory");
}

__device__ __forceinline__ void ldtm32(uint32_t* r, uint32_t addr) {
    asm volatile(
        "tcgen05.ld.sync.aligned.32x32b.x32.b32 "
        "{%0, %1, %2, %3, %4, %5, %6, %7, "
        " %8, %9, %10, %11, %12, %13, %14, %15, "
        " %16, %17, %18, %19, %20, %21, %22, %23, "
        " %24, %25, %26, %27, %28, %29, %30, %31}, [%32];"
        : "=r"(r[0]),  "=r"(r[1]),  "=r"(r[2]),  "=r"(r[3]),
          "=r"(r[4]),  "=r"(r[5]),  "=r"(r[6]),  "=r"(r[7]),
          "=r"(r[8]),  "=r"(r[9]),  "=r"(r[10]), "=r"(r[11]),
          "=r"(r[12]), "=r"(r[13]), "=r"(r[14]), "=r"(r[15]),
          "=r"(r[16]), "=r"(r[17]), "=r"(r[18]), "=r"(r[19]),
          "=r"(r[20]), "=r"(r[21]), "=r"(r[22]), "=r"(r[23]),
          "=r"(r[24]), "=r"(r[25]), "=r"(r[26]), "=r"(r[27]),
          "=r"(r[28]), "=r"(r[29]), "=r"(r[30]), "=r"(r[31])
        : "r"(addr));
}
#endif  // USE_TCGEN05

// C[M,N] = A[M,K] * B[N,K]^T, fp16 in, fp32 accum. M%256==0, N%512==0, K%64==0.
// 2-CTA cluster pair per (m,n) tile. cflag bit0: causal tile skip; bit1: causal K-limit.
template<bool OUT_HALF>
__global__ void __launch_bounds__(GEMM_THREADS, 1) __cluster_dims__(2, 1, 1)
hgemm(const __half* __restrict__ A, const __half* __restrict__ Bm, void* __restrict__ Cv,
      int M, int N, int K, long long sA, long long sB, long long sC,
      int lda, int ldb, int ldc, int cflag)
{
    extern __shared__ char dynsmem[];
    const int tid  = threadIdx.x;
    const int wid  = tid >> 5;
    const int rank = blockIdx.x & 1;                 // cluster cta rank
    const int m0 = blockIdx.y * BM;
    const int n0 = (blockIdx.x >> 1) * BN;
    if ((cflag & 1) && n0 >= m0 + BM + PAST) return; // fully masked score tile (pair-uniform)

    int nChunks = K >> 6;
    if (cflag & 2) {
        int lim = (m0 + BM + PAST) >> 6;
        if (lim < nChunks) nChunks = lim;
    }

    A  += (long long)blockIdx.z * sA;
    Bm += (long long)blockIdx.z * sB;

#if USE_TCGEN05
    // ===================== tcgen05 cg2 path =====================
    uint32_t raw  = (uint32_t)__cvta_generic_to_shared(dynsmem);
    uint32_t tb   = (raw + 1023u) & ~1023u;
    uint32_t ctrl = tb + NSTG * STAGE_BYTES;
    // ctrl+0: tmem ptr; full[s]=ctrl+8+8s (leader cnt 257, follower 256);
    // empty[s]=ctrl+40+8s (cnt 1); done=ctrl+72 (cnt 1)

    if (tid == 0) {
        #pragma unroll
        for (int s = 0; s < NSTG; s++) {
            mbar_init(ctrl + 8  + 8*s, (rank == 0) ? 257u : 256u);
            mbar_init(ctrl + 40 + 8*s, 1);
        }
        mbar_init(ctrl + 72, 1);
    }
    __syncthreads();
    if (wid == 8) {
        asm volatile("tcgen05.alloc.cta_group::2.sync.aligned.shared::cta.b32 [%0], %1;"
                     :: "r"(ctrl), "r"(512u) : "memory");
        asm volatile("tcgen05.relinquish_alloc_permit.cta_group::2.sync.aligned;");
    }
    __syncthreads();
    // cluster barrier: peer mbarriers + TMEM alloc visible before cross-CTA traffic
    asm volatile("barrier.cluster.arrive.aligned;" ::: "memory");
    asm volatile("barrier.cluster.wait.aligned;"   ::: "memory");

    uint32_t tmem;
    asm volatile("ld.shared.b32 %0, [%1];" : "=r"(tmem) : "r"(ctrl));

    if (wid < 8) {
        // ---------- producers (256 threads): A half + two B quarters ----------
        const int r0  = tid >> 3;          // 0..31
        const int c16 = tid & 7;
        uint32_t sw[4];
        #pragma unroll
        for (int i = 0; i < 4; i++) sw[i] = sw128((uint32_t)((r0 + 32*i) * 128 + c16 * 16));
        const __half* ap  = A  + (long long)(m0 + rank*128 + r0)        * lda + c16 * 8;
        const __half* b0p = Bm + (long long)(n0 + rank*128 + r0)        * ldb + c16 * 8;
        const __half* b1p = Bm + (long long)(n0 + 256 + rank*128 + r0)  * ldb + c16 * 8;
        const long long la32 = (long long)lda * 32, lb32 = (long long)ldb * 32;

        uint32_t ph = 1; int s = 0;
        for (int kc = 0; kc < nChunks; kc++) {
            mbar_wait(ctrl + 40 + 8*s, ph);
            uint32_t sb = tb + s * STAGE_BYTES;
            #pragma unroll
            for (int i = 0; i < 4; i++) cp_async16(sb + sw[i],          ap  + i * la32);
            #pragma unroll
            for (int i = 0; i < 4; i++) cp_async16(sb + 16384u + sw[i], b0p + i * lb32);
            #pragma unroll
            for (int i = 0; i < 4; i++) cp_async16(sb + 32768u + sw[i], b1p + i * lb32);
            cp_async_arrive(ctrl + 8 + 8*s);
            ap += BK; b0p += BK; b1p += BK;
            if (++s == NSTG) { s = 0; ph ^= 1; }
        }

        // ---------- epilogue: this CTA's 128 rows x 512 cols ----------
        mbar_wait(ctrl + 72, 0);
        asm volatile("tcgen05.fence::after_thread_sync;" ::: "memory");
        const int l = tid & 31;
        const int half = wid >> 2;                     // 0: cols 0-255, 1: cols 256-511
        const uint32_t dtm = tmem + half * 256u;
        const long long row = (long long)m0 + rank * 128 + (wid & 3) * 32 + l;
        const int colbase = n0 + half * 256;
        if (OUT_HALF) {
            __half* C = (__half*)Cv + blockIdx.z * sC + row * ldc + colbase;
            for (int b8 = 0; b8 < 8; b8++) {
                uint32_t r[32];
                ldtm32(r, dtm + b8 * 32);
                asm volatile("tcgen05.wait::ld.sync.aligned;" ::: "memory");
                uint32_t h[16];
                #pragma unroll
                for (int j = 0; j < 16; j++) {
                    __half2 hv = __floats2half2_rn(__uint_as_float(r[2*j]), __uint_as_float(r[2*j+1]));
                    h[j] = *reinterpret_cast<uint32_t*>(&hv);
                }
                uint4* dst = (uint4*)(C + b8 * 32);
                #pragma unroll
                for (int q = 0; q < 4; q++) dst[q] = make_uint4(h[4*q], h[4*q+1], h[4*q+2], h[4*q+3]);
            }
        } else {
            float* C = (float*)Cv + blockIdx.z * sC + row * ldc + colbase;
            for (int b8 = 0; b8 < 8; b8++) {
                uint32_t r[32];
                ldtm32(r, dtm + b8 * 32);
                asm volatile("tcgen05.wait::ld.sync.aligned;" ::: "memory");
                float4* dst = (float4*)(C + b8 * 32);
                #pragma unroll
                for (int q = 0; q < 8; q++)
                    dst[q] = make_float4(__uint_as_float(r[4*q]),   __uint_as_float(r[4*q+1]),
                                         __uint_as_float(r[4*q+2]), __uint_as_float(r[4*q+3]));
            }
        }
    } else if (rank == 0) {
        // ---------- leader MMA warp: ONE wait per chunk (full = 256 local + 1 fwd) ----------
        const uint32_t idesc = (1u << 4) | (32u << 17) | (16u << 24);
        uint32_t ph = 0; int s = 0;
        for (int kc = 0; kc < nChunks; kc++) {
            mbar_wait(ctrl + 8 + 8*s, ph);
            if (elect_one()) {
                asm volatile("fence.proxy.async.shared::cta;" ::: "memory");
                uint64_t ad = make_desc(tb + s * STAGE_BYTES);
                uint64_t b0 = make_desc(tb + s * STAGE_BYTES + 16384);
                uint64_t b1 = make_desc(tb + s * STAGE_BYTES + 32768);
                #pragma unroll
                for (int st = 0; st < 4; st++) {
                    uint32_t en = (kc == 0 && st == 0) ? 0u : 1u;
                    mma_f16_cg2(tmem,       ad + st * 2, b0 + st * 2, idesc, en);
                    mma_f16_cg2(tmem + 256, ad + st * 2, b1 + st * 2, idesc, en);
                }
                tc_commit_mc2(ctrl + 40 + 8*s);   // releases empty[s] in BOTH CTAs
            }
            if (++s == NSTG) { s = 0; ph ^= 1; }
        }
        if (elect_one()) tc_commit_mc2(ctrl + 72);  // done in BOTH CTAs
    } else {
        // ---------- follower forward warp: local full(256) -> leader full (257th) ----------
        uint32_t ph = 0; int s = 0;
        for (int kc = 0; kc < nChunks; kc++) {
            mbar_wait(ctrl + 8 + 8*s, ph);
            if (elect_one()) mbar_arrive_leader(ctrl + 8 + 8*s);
            if (++s == NSTG) { s = 0; ph ^= 1; }
        }
    }

    __syncthreads();
    if (wid == 8)
        asm volatile("tcgen05.dealloc.cta_group::2.sync.aligned.b32 %0, %1;" :: "r"(tmem), "r"(512u));
    asm volatile("barrier.cluster.arrive.aligned;" ::: "memory");
    asm volatile("barrier.cluster.wait.aligned;"   ::: "memory");

#else
    // ===================== mma.sync fallback (plain sm_103) =====================
    const int lane = tid & 31;
    const int g  = lane >> 2;
    const int tg = lane & 3;
    uint32_t sbase = (uint32_t)__cvta_generic_to_shared(dynsmem);
    sbase = (sbase + 127u) & ~127u;
    const uint32_t ST_A = 0, ST_B = 128 * 144, ST_SZ = 128 * 144 + 256 * 144;
    const int m0h = m0 + rank * 128;

    for (int nh = 0; nh < 2; nh++) {
        const int n0h = n0 + nh * 256;

        auto load_stage = [&](int s, int kk) {
            uint32_t sb = sbase + (uint32_t)s * ST_SZ;
            for (int idx = tid; idx < 3072; idx += GEMM_THREADS) {
                if (idx < 1024) {
                    int row = idx >> 3, c = idx & 7;
                    cp_async16(sb + ST_A + row * 144 + c * 16,
                               A + (long long)(m0h + row) * lda + kk + c * 8);
                } else {
                    int j = idx - 1024;
                    int row = j >> 3, c = j & 7;
                    cp_async16(sb + ST_B + row * 144 + c * 16,
                               Bm + (long long)(n0h + row) * ldb + kk + c * 8);
                }
            }
            asm volatile("cp.async.commit_group;" ::: "memory");
        };

        const int wm = (wid >> 1) * 32;
        const int wn = (wid & 1) * 128;

        float acc[16][4];
        #pragma unroll
        for (int jn = 0; jn < 16; jn++)
            #pragma unroll
            for (int q = 0; q < 4; q++) acc[jn][q] = 0.f;

        load_stage(0, 0);
        for (int kc = 0; kc < nChunks; kc++) {
            if (kc + 1 < nChunks) {
                load_stage((kc + 1) & 1, (kc + 1) * BK);
                asm volatile("cp.async.wait_group 1;" ::: "memory");
            } else {
                asm volatile("cp.async.wait_group 0;" ::: "memory");
            }
            __syncthreads();

            if (wid < 8) {
                uint32_t sb = sbase + (uint32_t)(kc & 1) * ST_SZ;
                #pragma unroll
                for (int k0 = 0; k0 < 64; k0 += 16) {
                    uint32_t a[2][2];
                    {
                        uint32_t r0a = sb + ST_A + (uint32_t)(wm + g) * 144 + (uint32_t)(k0 + tg * 2) * 2;
                        asm volatile("ld.shared.b32 %0, [%1];"        : "=r"(a[0][0]) : "r"(r0a));
                        asm volatile("ld.shared.b32 %0, [%1 + 1152];" : "=r"(a[0][1]) : "r"(r0a));
                        asm volatile("ld.shared.b32 %0, [%1 + 16];"   : "=r"(a[1][0]) : "r"(r0a));
                        asm volatile("ld.shared.b32 %0, [%1 + 1168];" : "=r"(a[1][1]) : "r"(r0a));
                    }
                    #pragma unroll
                    for (int jn = 0; jn < 16; jn++) {
                        uint32_t b0, b1;
                        uint32_t rb = sb + ST_B + (uint32_t)(wn + jn * 8 + g) * 144 + (uint32_t)(k0 + tg * 2) * 2;
                        asm volatile("ld.shared.b32 %0, [%1];"      : "=r"(b0) : "r"(rb));
                        asm volatile("ld.shared.b32 %0, [%1 + 16];" : "=r"(b1) : "r"(rb));
                        asm volatile(
                            "mma.sync.aligned.m16n8k16.row.col.f32.f16.f16.f32 "
                            "{%0,%1,%2,%3}, {%4,%5,%6,%7}, {%8,%9}, {%0,%1,%2,%3};"
                            : "+f"(acc[jn][0]), "+f"(acc[jn][1]),
                              "+f"(acc[jn][2]), "+f"(acc[jn][3])
                            : "r"(a[0][0]), "r"(a[0][1]), "r"(a[1][0]), "r"(a[1][1]),
                              "r"(b0), "r"(b1));
                    }
                }
            }
            __syncthreads();
        }

        if (wid < 8) {
            const long long r0w = (long long)m0h + wm + g;
            #pragma unroll
            for (int jn = 0; jn < 16; jn++) {
                const long long cc = (long long)n0h + wn + jn * 8 + tg * 2;
                if (OUT_HALF) {
                    __half* C = (__half*)Cv + blockIdx.z * sC;
                    *(__half2*)(C + r0w * ldc + cc)       = __floats2half2_rn(acc[jn][0], acc[jn][1]);
                    *(__half2*)(C + (r0w + 8) * ldc + cc) = __floats2half2_rn(acc[jn][2], acc[jn][3]);
                } else {
                    float* C = (float*)Cv + blockIdx.z * sC;
                    float* p0 = C + r0w * ldc + cc;
                    float* p1 = C + (r0w + 8) * ldc + cc;
                    p0[0] = acc[jn][0]; p0[1] = acc[jn][1];
                    p1[0] = acc[jn][2]; p1[1] = acc[jn][3];
                }
            }
        }
        __syncthreads();
    }
#endif
}

// ================= elementwise kernels =================
__device__ __forceinline__ uint32_t h2bits(__half2 h) { return *reinterpret_cast<uint32_t*>(&h); }

__global__ void cvt_f32_f16(const float* __restrict__ in, __half* __restrict__ out, int n8) {
    int i = blockIdx.x * 256 + threadIdx.x;
    if (i < n8) {
        float4 a = ((const float4*)in)[2*i], b = ((const float4*)in)[2*i+1];
        uint4 o;
        o.x = h2bits(__floats2half2_rn(a.x, a.y));
        o.y = h2bits(__floats2half2_rn(a.z, a.w));
        o.z = h2bits(__floats2half2_rn(b.x, b.y));
        o.w = h2bits(__floats2half2_rn(b.z, b.w));
        ((uint4*)out)[i] = o;
    }
}

__global__ void cvt_weights6(const float* s0, const float* s1, const float* s2,
                             const float* s3, const float* s4, const float* s5,
                             __half* d0, __half* d1, __half* d2,
                             __half* d3, __half* d4, __half* d5) {
    int i = blockIdx.x * 256 + threadIdx.x;
    int w = i >> 17;
    int j = i & 131071;
    const float* s; __half* d;
    switch (w) {
        case 0: s = s0; d = d0; break;
        case 1: s = s1; d = d1; break;
        case 2: s = s2; d = d2; break;
        case 3: s = s3; d = d3; break;
        case 4: s = s4; d = d4; break;
        default: s = s5; d = d5; break;
    }
    const float sc = (w == 1 || w == 4) ? QSCALE : 1.0f;
    float4 a = ((const float4*)s)[2*j], b = ((const float4*)s)[2*j+1];
    uint4 o;
    o.x = h2bits(__floats2half2_rn(a.x * sc, a.y * sc));
    o.y = h2bits(__floats2half2_rn(a.z * sc, a.w * sc));
    o.z = h2bits(__floats2half2_rn(b.x * sc, b.y * sc));
    o.w = h2bits(__floats2half2_rn(b.z * sc, b.w * sc));
    ((uint4*)d)[j] = o;
}

__global__ void transpose_f32_f16(const float* __restrict__ in, __half* __restrict__ out, int R, int C) {
    __shared__ float t[32][33];
    int bx = blockIdx.x * 32, by = blockIdx.y * 32;
    #pragma unroll
    for (int j = 0; j < 32; j += 8)
        t[threadIdx.y + j][threadIdx.x] = in[(long long)(by + threadIdx.y + j) * C + bx + threadIdx.x];
    __syncthreads();
    #pragma unroll
    for (int j = 0; j < 32; j += 8)
        out[(long long)(bx + threadIdx.y + j) * R + by + threadIdx.x] =
            __float2half_rn(t[threadIdx.x][threadIdx.y + j]);
}

__global__ void copy_cache(const float* __restrict__ src, float* __restrict__ dstF,
                           __half* __restrict__ dstH, int hcol) {
    int row = blockIdx.x; int b = row / PAST, r = row % PAST;
    const float4* s  = (const float4*)(src + (size_t)row * 1024);
    float4* dF = (float4*)(dstF + ((size_t)b * STOT + r) * 1024);
    __half* dH = dstH + ((size_t)b * STOT + r) * 2048 + hcol;
    int j = threadIdx.x;
    float4 v = s[j];
    dF[j] = v;
    uint2 u; u.x = h2bits(__floats2half2_rn(v.x, v.y)); u.y = h2bits(__floats2half2_rn(v.z, v.w));
    *(uint2*)(dH + j * 4) = u;
}

__device__ __forceinline__ float blk_sum(float v, float* red) {
    const int tid = threadIdx.x;
    #pragma unroll
    for (int o = 16; o > 0; o >>= 1) v += __shfl_xor_sync(0xffffffffu, v, o);
    if ((tid & 31) == 0) red[tid >> 5] = v;
    __syncthreads();
    float t = (tid < 8) ? red[tid] : 0.f;
    if (tid < 32) {
        #pragma unroll
        for (int o = 4; o > 0; o >>= 1) t += __shfl_xor_sync(0xffffffffu, t, o);
        if (tid == 0) red[0] = t;
    }
    __syncthreads();
    float r = red[0];
    __syncthreads();
    return r;
}

__device__ __forceinline__ float blk_max(float v, float* red) {
    const int tid = threadIdx.x;
    #pragma unroll
    for (int o = 16; o > 0; o >>= 1) v = fmaxf(v, __shfl_xor_sync(0xffffffffu, v, o));
    if ((tid & 31) == 0) red[tid >> 5] = v;
    __syncthreads();
    float t = (tid < 8) ? red[tid] : -3.4e38f;
    if (tid < 32) {
        #pragma unroll
        for (int o = 4; o > 0; o >>= 1) t = fmaxf(t, __shfl_xor_sync(0xffffffffu, t, o));
        if (tid == 0) red[0] = t;
    }
    __syncthreads();
    float r = red[0];
    __syncthreads();
    return r;
}

__global__ void layernorm_kernel(const float* __restrict__ c, float* __restrict__ ckv,
                                 __half* __restrict__ kcat,
                                 const float* __restrict__ g, const float* __restrict__ b) {
    const int row = blockIdx.x; const int bb = row / SEQ, si = row % SEQ;
    const float* p = c + (size_t)row * LDIM;
    float*  o  = ckv  + ((size_t)bb * STOT + PAST + si) * 1024;
    __half* oh = kcat + ((size_t)bb * STOT + PAST + si) * 2048;
    __shared__ float red[8];
    const int tid = threadIdx.x;
    float s = 0.f, s2 = 0.f;
    for (int j = tid; j < LDIM; j += 256) { float v = p[j]; s += v; s2 += v * v; }
    s  = blk_sum(s,  red);
    s2 = blk_sum(s2, red);
    const float mean = s * (1.f / LDIM);
    const float var  = fmaxf(s2 * (1.f / LDIM) - mean * mean, 0.f);
    const float inv  = rsqrtf(var + 1e-5f);
    for (int j = tid; j < LDIM; j += 256) {
        float v = (p[j] - mean) * inv * g[j] + b[j];
        o[j] = v; oh[j] = __float2half_rn(v);
    }
}

// rope on krp (fp16) -> d_out kr tail (fp32) + Kcat right half (fp16)
__global__ void rope_k_kernel(const __half* __restrict__ in, float* __restrict__ kr,
                              __half* __restrict__ kcat) {
    const int row = blockIdx.x; const int bb = row / SEQ, t = row % SEQ;
    const int j = threadIdx.x;
    const __half* pi = in + (size_t)row * 1024;
    float*  po = kr   + ((size_t)bb * STOT + PAST + t) * 1024;
    __half* ph = kcat + ((size_t)bb * STOT + PAST + t) * 2048 + 1024;
    float x1 = __half2float(pi[j]), x2 = __half2float(pi[j + 512]);
    const float inv_freq = powf(10000.f, -(float)(2 * j) * (1.f / 1024.f));
    float sn, cs; sincosf((float)t * inv_freq, &sn, &cs);
    float y1 = x1 * cs - x2 * sn, y2 = x2 * cs + x1 * sn;
    po[j] = y1; po[j + 512] = y2;
    ph[j] = __float2half_rn(y1); ph[j + 512] = __float2half_rn(y2);
}

// rope on (qpre fp16 + QSCALE*bqr) -> Qcat right half (fp16)
__global__ void rope_q_kernel(const __half* __restrict__ in, __half* __restrict__ qcat,
                              const float* __restrict__ bias) {
    const int row = blockIdx.x; const int t = row % SEQ;
    const int j = threadIdx.x;
    const __half* pi = in + (size_t)row * 1024;
    __half* ph = qcat + (size_t)row * 2048 + 1024;
    float x1 = __half2float(pi[j]) + QSCALE * bias[j];
    float x2 = __half2float(pi[j + 512]) + QSCALE * bias[j + 512];
    const float inv_freq = powf(10000.f, -(float)(2 * j) * (1.f / 1024.f));
    float sn, cs; sincosf((float)t * inv_freq, &sn, &cs);
    ph[j]       = __float2half_rn(x1 * cs - x2 * sn);
    ph[j + 512] = __float2half_rn(x2 * cs + x1 * sn);
}

// masked softmax: scores fp32 (pre-scaled) -> w fp16  (all batches, grid B*SEQ)
__global__ void softmax_kernel(const float* __restrict__ sc, __half* __restrict__ wh) {
    const int row = blockIdx.x;
    const int si  = row % SEQ;
    const int valid = si + PAST + 1;
    const float* p = sc + (size_t)row * STOT;
    __half* o = wh + (size_t)row * STOT;
    __shared__ float buf[STOT];
    __shared__ float red[8];
    const int tid = threadIdx.x;

    float mx = -3.4e38f;
    for (int j = tid; j < valid; j += 256) { float v = p[j]; buf[j] = v; mx = fmaxf(mx, v); }
    mx = blk_max(mx, red);
    float sum = 0.f;
    for (int j = tid; j < valid; j += 256) { float e = __expf(buf[j] - mx); buf[j] = e; sum += e; }
    sum = blk_sum(sum, red);
    const float inv = 1.f / sum;
    for (int j = tid; j < valid; j += 256) o[j] = __float2half_rn(buf[j] * inv);
    for (int j = valid + tid; j < STOT; j += 256) o[j] = __float2half_rn(0.f);
}

// ================= launch =================
extern "C" void kernel_launch(void* const* d_in, const int* in_sizes, int n_in,
                              void* d_out, int out_size)
{
    (void)in_sizes; (void)n_in; (void)out_size;
    const float* x        = (const float*)d_in[0];
    const float* kv_cache = (const float*)d_in[1];
    const float* kr_cache = (const float*)d_in[2];
    const float* Wq       = (const float*)d_in[3];
    const float* Wdkv     = (const float*)d_in[4];
    const float* Wuk      = (const float*)d_in[5];
    const float* Wuv      = (const float*)d_in[6];
    const float* Wo       = (const float*)d_in[7];
    const float* Wkr      = (const float*)d_in[8];
    const float* Wqr      = (const float*)d_in[9];
    const float* bqr      = (const float*)d_in[10];
    const float* ln_g     = (const float*)d_in[11];
    const float* ln_b     = (const float*)d_in[12];

    float* out = (float*)d_out;
    float* ckv = out + (size_t)B_ * SEQ * EDIM;
    float* kr  = ckv + (size_t)B_ * STOT * LDIM;

    __half *xh, *wqh, *wukh, *wdkvh, *wkrh, *wqrh, *woh, *wuvTh, *absTh, *Kcat, *Qcat, *wh, *vTh, *atth;
    __half *krp, *qpre;
    float *c, *sc;
    cudaGetSymbolAddress((void**)&xh,    g_xh);
    cudaGetSymbolAddress((void**)&wqh,   g_Wqh);
    cudaGetSymbolAddress((void**)&wukh,  g_Wukh);
    cudaGetSymbolAddress((void**)&wdkvh, g_Wdkvh);
    cudaGetSymbolAddress((void**)&wkrh,  g_Wkrh);
    cudaGetSymbolAddress((void**)&wqrh,  g_Wqrh);
    cudaGetSymbolAddress((void**)&woh,   g_Woh);
    cudaGetSymbolAddress((void**)&wuvTh, g_WuvTh);
    cudaGetSymbolAddress((void**)&absTh, g_absTh);
    cudaGetSymbolAddress((void**)&c,     g_c);
    cudaGetSymbolAddress((void**)&krp,   g_krp);
    cudaGetSymbolAddress((void**)&qpre,  g_qpre);
    cudaGetSymbolAddress((void**)&Kcat,  g_Kcat);
    cudaGetSymbolAddress((void**)&Qcat,  g_Qcat);
    cudaGetSymbolAddress((void**)&sc,    g_sc);
    cudaGetSymbolAddress((void**)&wh,    g_wh);
    cudaGetSymbolAddress((void**)&vTh,   g_vTh);
    cudaGetSymbolAddress((void**)&atth,  g_atth);

    cudaFuncSetAttribute(hgemm<false>, cudaFuncAttributeMaxDynamicSharedMemorySize, GEMM_SMEM);
    cudaFuncSetAttribute(hgemm<true>,  cudaFuncAttributeMaxDynamicSharedMemorySize, GEMM_SMEM);

    // ---- proven topology: 3 streams, 9 events, single-use ----
    static cudaStream_t st[3] = {nullptr, nullptr, nullptr};
    static cudaEvent_t  ev[10] = {};
    if (st[0] == nullptr) {
        for (int i = 0; i < 3; i++) cudaStreamCreateWithFlags(&st[i], cudaStreamNonBlocking);
        for (int i = 0; i < 10; i++) cudaEventCreateWithFlags(&ev[i], cudaEventDisableTiming);
    }
    cudaEvent_t eFork = ev[0], eX = ev[1], eW = ev[2], eXa = ev[3], eT = ev[4],
                eRk = ev[5], eCc = ev[6], eLN = ev[7], eV = ev[8];

    const long long sL2 = (long long)SEQ * 2048;
    const long long SL2 = (long long)STOT * 2048;
    const long long sS  = (long long)SEQ * STOT;
    const long long sE  = (long long)SEQ * 1024;
    const long long ES  = (long long)EDIM * STOT;

    // ---------------- FORK ----------------
    cudaEventRecord(eFork, 0);
    for (int i = 0; i < 3; i++) cudaStreamWaitEvent(st[i], eFork, 0);

    cvt_f32_f16<<<4096, 256>>>(x, xh, (B_*SEQ*EDIM)/8);
    cudaEventRecord(eX, 0);

    // st[0]: weights cvt -> absT -> xa (Qcat left)
    cvt_weights6<<<3072, 256, 0, st[0]>>>(Wq, Wuk, Wdkv, Wkr, Wqr, Wo,
                                          wqh, wukh, wdkvh, wkrh, wqrh, woh);
    cudaEventRecord(eW, st[0]);
    hgemm<true><<<dim3(4, 4, 1), GEMM_THREADS, GEMM_SMEM, st[0]>>>(
        wukh, wqh, absTh, 1024, 1024, 1024, 0, 0, 0, 1024, 1024, 1024, 0);
    cudaStreamWaitEvent(st[0], eX, 0);
    hgemm<true><<<dim3(4, 32, 1), GEMM_THREADS, GEMM_SMEM, st[0]>>>(
        xh, absTh, Qcat, 8192, 1024, 1024, 0, 0, 0, 1024, 1024, 2048, 0);
    cudaEventRecord(eXa, st[0]);

    // st[1]: Wuv transpose, then krp (fp16) -> rope_k
    transpose_f32_f16<<<dim3(32, 32), dim3(32, 8), 0, st[1]>>>(Wuv, wuvTh, LDIM, EDIM);
    cudaEventRecord(eT, st[1]);
    cudaStreamWaitEvent(st[1], eX, 0);
    cudaStreamWaitEvent(st[1], eW, 0);
    hgemm<true><<<dim3(4, 32, 1), GEMM_THREADS, GEMM_SMEM, st[1]>>>(
        xh, wkrh, krp, 8192, 1024, 1024, 0, 0, 0, 1024, 1024, 1024, 0);
    rope_k_kernel<<<B_*SEQ, 512, 0, st[1]>>>(krp, kr, Kcat);
    cudaEventRecord(eRk, st[1]);

    // st[2]: cache copies
    copy_cache<<<B_*PAST, 256, 0, st[2]>>>(kv_cache, ckv, Kcat, 0);
    copy_cache<<<B_*PAST, 256, 0, st[2]>>>(kr_cache, kr,  Kcat, 1024);
    cudaEventRecord(eCc, st[2]);

    // main: c -> LN -> qpre (fp16) -> rope_q (critical path)
    cudaStreamWaitEvent(0, eW, 0);
    hgemm<false><<<dim3(4, 32, 1), GEMM_THREADS, GEMM_SMEM>>>(
        xh, wdkvh, c, 8192, 1024, 1024, 0, 0, 0, 1024, 1024, 1024, 0);
    layernorm_kernel<<<B_*SEQ, 256>>>(c, ckv, Kcat, ln_g, ln_b);
    cudaEventRecord(eLN, 0);
    hgemm<true><<<dim3(4, 8, 4), GEMM_THREADS, GEMM_SMEM>>>(
        Kcat + (size_t)PAST * 2048, wqrh, qpre, 2048, 1024, 1024,
        SL2, 0, sE, 2048, 1024, 1024, 0);
    rope_q_kernel<<<B_*SEQ, 512>>>(qpre, Qcat, bqr);

    // st[2]: valueT — overlaps scores+softmax
    cudaStreamWaitEvent(st[2], eLN, 0);
    cudaStreamWaitEvent(st[2], eT, 0);
    hgemm<true><<<dim3(16, 4, 4), GEMM_THREADS, GEMM_SMEM, st[2]>>>(
        wuvTh, Kcat, vTh, 1024, 4096, 1024, 0, SL2, ES, 1024, 2048, 4096, 0);
    cudaEventRecord(eV, st[2]);

    // ---------------- JOIN for scores ----------------
    cudaStreamWaitEvent(0, eXa, 0);
    cudaStreamWaitEvent(0, eRk, 0);
    cudaStreamWaitEvent(0, eCc, 0);

    // scores = Qcat @ Kcat^T (pre-scaled; K=2048; causal tile skip)
    hgemm<false><<<dim3(16, 8, 4), GEMM_THREADS, GEMM_SMEM>>>(
        Qcat, Kcat, sc, 2048, 4096, 2048, sL2, SL2, sS, 2048, 2048, 4096, 1);

    softmax_kernel<<<B_*SEQ, 256>>>(sc, wh);

    // att = w @ valueT^T (causal K-limit)
    cudaStreamWaitEvent(0, eV, 0);
    hgemm<true><<<dim3(4, 8, 4), GEMM_THREADS, GEMM_SMEM>>>(
        wh, vTh, atth, 2048, 1024, 4096, sS, ES, sE, 4096, 4096, 1024, 2);

    // out = att @ Wo^T
    hgemm<false><<<dim3(4, 32, 1), GEMM_THREADS, GEMM_SMEM>>>(
        atth, woh, out, 8192, 1024, 1024, 0, 0, 0, 1024, 1024, 1024, 0);
}

// round 15
// speedup vs baseline: 1.0843x; 1.0364x over previous
#include <cuda_runtime.h>
#include <cuda_fp16.h>
#include <math.h>
#include <stdint.h>

// ---------------- fixed problem shapes ----------------
#define B_    4
#define SEQ   2048
#define PAST  2048
#define EDIM  1024
#define LDIM  1024
#define STOT  4096
#define QSCALE 0.022097086912079608f   // 1/sqrt(2*LDIM)

// ---------------- scratch (device globals) ----------------
__device__ __align__(256) __half g_xh    [(size_t)B_*SEQ*EDIM];
__device__ __align__(256) __half g_Wqh   [EDIM*EDIM];
__device__ __align__(256) __half g_Wukh  [LDIM*EDIM];
__device__ __align__(256) __half g_Wdkvh [LDIM*EDIM];
__device__ __align__(256) __half g_Wkrh  [LDIM*EDIM];
__device__ __align__(256) __half g_Wqrh  [EDIM*LDIM];
__device__ __align__(256) __half g_Woh   [EDIM*EDIM];
__device__ __align__(256) __half g_Wuvh  [LDIM*EDIM];
__device__ __align__(256) __half g_WuvWoT[EDIM*LDIM];   // (Wuv @ Wo^T)^T = Wo @ Wuv^T
__device__ __align__(256) __half g_absTh [LDIM*EDIM];
__device__ __align__(256) float  g_c     [(size_t)B_*SEQ*LDIM];
__device__ __align__(256) __half g_krp   [(size_t)B_*SEQ*LDIM];
__device__ __align__(256) __half g_qpre  [(size_t)B_*SEQ*EDIM];
__device__ __align__(256) __half g_Kcat  [(size_t)B_*STOT*2048];  // [ckv | kr] fp16
__device__ __align__(256) __half g_Qcat  [(size_t)B_*SEQ*2048];   // [xa | q_r] fp16
__device__ __align__(256) float  g_sc    [(size_t)B_*SEQ*STOT];
__device__ __align__(256) __half g_wh    [(size_t)B_*SEQ*STOT];
__device__ __align__(256) __half g_vTh   [(size_t)B_*EDIM*STOT];  // (value@Wo^T)^T per batch [E,S]

// ================= GEMM config (R9/R14 best) =================
#define BM 256
#define BN 512
#define BK 64
#define NSTG 4
#define STAGE_BYTES 49152
#define GEMM_THREADS 288
#define GEMM_SMEM (NSTG*STAGE_BYTES + 1024 + 128)

#if defined(__CUDA_ARCH__) && (defined(__CUDA_ARCH_FEAT_SM103_ALL) || defined(__CUDA_ARCH_FEAT_SM100_ALL) || defined(__CUDA_ARCH_FEAT_SM101_ALL))
#define USE_TCGEN05 1
#else
#define USE_TCGEN05 0
#endif

__device__ __forceinline__ void cp_async16(uint32_t dst, const void* src) {
    asm volatile("cp.async.cg.shared.global [%0], [%1], 16;" :: "r"(dst), "l"(src) : "memory");
}

#if USE_TCGEN05
__device__ __forceinline__ uint32_t sw128(uint32_t o) { return o ^ ((o >> 3) & 0x70u); }

__device__ __forceinline__ uint64_t make_desc(uint32_t addr) {
    return ((uint64_t)2 << 61) | (1ull << 46) | (64ull << 32) | (1ull << 16)
         | ((addr >> 4) & 0x3FFFull);
}

__device__ __forceinline__ bool elect_one() {
    uint32_t pred;
    asm volatile("{\n\t.reg .pred p;\n\telect.sync _|p, 0xFFFFFFFF;\n\tselp.b32 %0, 1, 0, p;\n\t}"
                 : "=r"(pred));
    return pred != 0;
}

__device__ __forceinline__ void mbar_init(uint32_t a, uint32_t cnt) {
    asm volatile("mbarrier.init.shared.b64 [%0], %1;" :: "r"(a), "r"(cnt) : "memory");
}

__device__ __forceinline__ void mbar_wait(uint32_t a, uint32_t ph) {
    asm volatile(
        "{\n\t.reg .pred P;\n"
        "LW%=:\n\t"
        "mbarrier.try_wait.parity.acquire.cta.shared::cta.b64 P, [%0], %1, 0x989680;\n\t"
        "@!P bra LW%=;\n\t}"
        :: "r"(a), "r"(ph) : "memory");
}

__device__ __forceinline__ void cp_async_arrive(uint32_t bar) {
    asm volatile("cp.async.mbarrier.arrive.noinc.shared::cta.b64 [%0];" :: "r"(bar) : "memory");
}

__device__ __forceinline__ void mbar_arrive_leader(uint32_t local_addr) {
    asm volatile(
        "{\n\t.reg .b32 remAddr;\n\t"
        "mapa.shared::cluster.u32 remAddr, %0, 0;\n\t"
        "mbarrier.arrive.shared::cluster.b64 _, [remAddr];\n\t}"
        :: "r"(local_addr) : "memory");
}

__device__ __forceinline__ void mma_f16_cg2(uint32_t d, uint64_t ad, uint64_t bd,
                                            uint32_t idesc, uint32_t en) {
    asm volatile(
        "{\n\t.reg .pred p;\n\tsetp.ne.u32 p, %4, 0;\n\t"
        "tcgen05.mma.cta_group::2.kind::f16 [%0], %1, %2, %3, "
        "{%5, %5, %5, %5, %5, %5, %5, %5}, p;\n\t}"
        :: "r"(d), "l"(ad), "l"(bd), "r"(idesc), "r"(en), "r"(0u) : "memory");
}

__device__ __forceinline__ void tc_commit_mc2(uint32_t bar) {
    asm volatile(
        "tcgen05.commit.cta_group::2.mbarrier::arrive::one.shared::cluster.multicast::cluster.b64 [%0], %1;"
        :: "r"(bar), "h"((uint16_t)3) : "memory");
}

__device__ __forceinline__ void ldtm32(uint32_t* r, uint32_t addr) {
    asm volatile(
        "tcgen05.ld.sync.aligned.32x32b.x32.b32 "
        "{%0, %1, %2, %3, %4, %5, %6, %7, "
        " %8, %9, %10, %11, %12, %13, %14, %15, "
        " %16, %17, %18, %19, %20, %21, %22, %23, "
        " %24, %25, %26, %27, %28, %29, %30, %31}, [%32];"
        : "=r"(r[0]),  "=r"(r[1]),  "=r"(r[2]),  "=r"(r[3]),
          "=r"(r[4]),  "=r"(r[5]),  "=r"(r[6]),  "=r"(r[7]),
          "=r"(r[8]),  "=r"(r[9]),  "=r"(r[10]), "=r"(r[11]),
          "=r"(r[12]), "=r"(r[13]), "=r"(r[14]), "=r"(r[15]),
          "=r"(r[16]), "=r"(r[17]), "=r"(r[18]), "=r"(r[19]),
          "=r"(r[20]), "=r"(r[21]), "=r"(r[22]), "=r"(r[23]),
          "=r"(r[24]), "=r"(r[25]), "=r"(r[26]), "=r"(r[27]),
          "=r"(r[28]), "=r"(r[29]), "=r"(r[30]), "=r"(r[31])
        : "r"(addr));
}
#endif  // USE_TCGEN05

// C[M,N] = A[M,K] * B[N,K]^T, fp16 in, fp32 accum. M%256==0, N%512==0, K%64==0.
// 2-CTA cluster pair per (m,n) tile. cflag bit0: causal tile skip; bit1: causal K-limit.
template<bool OUT_HALF>
__global__ void __launch_bounds__(GEMM_THREADS, 1) __cluster_dims__(2, 1, 1)
hgemm(const __half* __restrict__ A, const __half* __restrict__ Bm, void* __restrict__ Cv,
      int M, int N, int K, long long sA, long long sB, long long sC,
      int lda, int ldb, int ldc, int cflag)
{
    extern __shared__ char dynsmem[];
    const int tid  = threadIdx.x;
    const int wid  = tid >> 5;
    const int rank = blockIdx.x & 1;
    const int m0 = blockIdx.y * BM;
    const int n0 = (blockIdx.x >> 1) * BN;
    if ((cflag & 1) && n0 >= m0 + BM + PAST) return;

    int nChunks = K >> 6;
    if (cflag & 2) {
        int lim = (m0 + BM + PAST) >> 6;
        if (lim < nChunks) nChunks = lim;
    }

    A  += (long long)blockIdx.z * sA;
    Bm += (long long)blockIdx.z * sB;

#if USE_TCGEN05
    uint32_t raw  = (uint32_t)__cvta_generic_to_shared(dynsmem);
    uint32_t tb   = (raw + 1023u) & ~1023u;
    uint32_t ctrl = tb + NSTG * STAGE_BYTES;

    if (tid == 0) {
        #pragma unroll
        for (int s = 0; s < NSTG; s++) {
            mbar_init(ctrl + 8  + 8*s, (rank == 0) ? 257u : 256u);
            mbar_init(ctrl + 40 + 8*s, 1);
        }
        mbar_init(ctrl + 72, 1);
    }
    __syncthreads();
    if (wid == 8) {
        asm volatile("tcgen05.alloc.cta_group::2.sync.aligned.shared::cta.b32 [%0], %1;"
                     :: "r"(ctrl), "r"(512u) : "memory");
        asm volatile("tcgen05.relinquish_alloc_permit.cta_group::2.sync.aligned;");
    }
    __syncthreads();
    asm volatile("barrier.cluster.arrive.aligned;" ::: "memory");
    asm volatile("barrier.cluster.wait.aligned;"   ::: "memory");

    uint32_t tmem;
    asm volatile("ld.shared.b32 %0, [%1];" : "=r"(tmem) : "r"(ctrl));

    if (wid < 8) {
        const int r0  = tid >> 3;
        const int c16 = tid & 7;
        uint32_t sw[4];
        #pragma unroll
        for (int i = 0; i < 4; i++) sw[i] = sw128((uint32_t)((r0 + 32*i) * 128 + c16 * 16));
        const __half* ap  = A  + (long long)(m0 + rank*128 + r0)        * lda + c16 * 8;
        const __half* b0p = Bm + (long long)(n0 + rank*128 + r0)        * ldb + c16 * 8;
        const __half* b1p = Bm + (long long)(n0 + 256 + rank*128 + r0)  * ldb + c16 * 8;
        const long long la32 = (long long)lda * 32, lb32 = (long long)ldb * 32;

        uint32_t ph = 1; int s = 0;
        for (int kc = 0; kc < nChunks; kc++) {
            mbar_wait(ctrl + 40 + 8*s, ph);
            uint32_t sb = tb + s * STAGE_BYTES;
            #pragma unroll
            for (int i = 0; i < 4; i++) cp_async16(sb + sw[i],          ap  + i * la32);
            #pragma unroll
            for (int i = 0; i < 4; i++) cp_async16(sb + 16384u + sw[i], b0p + i * lb32);
            #pragma unroll
            for (int i = 0; i < 4; i++) cp_async16(sb + 32768u + sw[i], b1p + i * lb32);
            cp_async_arrive(ctrl + 8 + 8*s);
            ap += BK; b0p += BK; b1p += BK;
            if (++s == NSTG) { s = 0; ph ^= 1; }
        }

        mbar_wait(ctrl + 72, 0);
        asm volatile("tcgen05.fence::after_thread_sync;" ::: "memory");
        const int l = tid & 31;
        const int half = wid >> 2;
        const uint32_t dtm = tmem + half * 256u;
        const long long row = (long long)m0 + rank * 128 + (wid & 3) * 32 + l;
        const int colbase = n0 + half * 256;
        if (OUT_HALF) {
            __half* C = (__half*)Cv + blockIdx.z * sC + row * ldc + colbase;
            for (int b8 = 0; b8 < 8; b8++) {
                uint32_t r[32];
                ldtm32(r, dtm + b8 * 32);
                asm volatile("tcgen05.wait::ld.sync.aligned;" ::: "memory");
                uint32_t h[16];
                #pragma unroll
                for (int j = 0; j < 16; j++) {
                    __half2 hv = __floats2half2_rn(__uint_as_float(r[2*j]), __uint_as_float(r[2*j+1]));
                    h[j] = *reinterpret_cast<uint32_t*>(&hv);
                }
                uint4* dst = (uint4*)(C + b8 * 32);
                #pragma unroll
                for (int q = 0; q < 4; q++) dst[q] = make_uint4(h[4*q], h[4*q+1], h[4*q+2], h[4*q+3]);
            }
        } else {
            float* C = (float*)Cv + blockIdx.z * sC + row * ldc + colbase;
            for (int b8 = 0; b8 < 8; b8++) {
                uint32_t r[32];
                ldtm32(r, dtm + b8 * 32);
                asm volatile("tcgen05.wait::ld.sync.aligned;" ::: "memory");
                float4* dst = (float4*)(C + b8 * 32);
                #pragma unroll
                for (int q = 0; q < 8; q++)
                    dst[q] = make_float4(__uint_as_float(r[4*q]),   __uint_as_float(r[4*q+1]),
                                         __uint_as_float(r[4*q+2]), __uint_as_float(r[4*q+3]));
            }
        }
    } else if (rank == 0) {
        const uint32_t idesc = (1u << 4) | (32u << 17) | (16u << 24);
        uint32_t ph = 0; int s = 0;
        for (int kc = 0; kc < nChunks; kc++) {
            mbar_wait(ctrl + 8 + 8*s, ph);
            if (elect_one()) {
                asm volatile("fence.proxy.async.shared::cta;" ::: "memory");
                uint64_t ad = make_desc(tb + s * STAGE_BYTES);
                uint64_t b0 = make_desc(tb + s * STAGE_BYTES + 16384);
                uint64_t b1 = make_desc(tb + s * STAGE_BYTES + 32768);
                #pragma unroll
                for (int st = 0; st < 4; st++) {
                    uint32_t en = (kc == 0 && st == 0) ? 0u : 1u;
                    mma_f16_cg2(tmem,       ad + st * 2, b0 + st * 2, idesc, en);
                    mma_f16_cg2(tmem + 256, ad + st * 2, b1 + st * 2, idesc, en);
                }
                tc_commit_mc2(ctrl + 40 + 8*s);
            }
            if (++s == NSTG) { s = 0; ph ^= 1; }
        }
        if (elect_one()) tc_commit_mc2(ctrl + 72);
    } else {
        uint32_t ph = 0; int s = 0;
        for (int kc = 0; kc < nChunks; kc++) {
            mbar_wait(ctrl + 8 + 8*s, ph);
            if (elect_one()) mbar_arrive_leader(ctrl + 8 + 8*s);
            if (++s == NSTG) { s = 0; ph ^= 1; }
        }
    }

    __syncthreads();
    if (wid == 8)
        asm volatile("tcgen05.dealloc.cta_group::2.sync.aligned.b32 %0, %1;" :: "r"(tmem), "r"(512u));
    asm volatile("barrier.cluster.arrive.aligned;" ::: "memory");
    asm volatile("barrier.cluster.wait.aligned;"   ::: "memory");

#else
    // ===================== mma.sync fallback (plain sm_103) =====================
    const int lane = tid & 31;
    const int g  = lane >> 2;
    const int tg = lane & 3;
    uint32_t sbase = (uint32_t)__cvta_generic_to_shared(dynsmem);
    sbase = (sbase + 127u) & ~127u;
    const uint32_t ST_A = 0, ST_B = 128 * 144, ST_SZ = 128 * 144 + 256 * 144;
    const int m0h = m0 + rank * 128;

    for (int nh = 0; nh < 2; nh++) {
        const int n0h = n0 + nh * 256;

        auto load_stage = [&](int s, int kk) {
            uint32_t sb = sbase + (uint32_t)s * ST_SZ;
            for (int idx = tid; idx < 3072; idx += GEMM_THREADS) {
                if (idx < 1024) {
                    int row = idx >> 3, c = idx & 7;
                    cp_async16(sb + ST_A + row * 144 + c * 16,
                               A + (long long)(m0h + row) * lda + kk + c * 8);
                } else {
                    int j = idx - 1024;
                    int row = j >> 3, c = j & 7;
                    cp_async16(sb + ST_B + row * 144 + c * 16,
                               Bm + (long long)(n0h + row) * ldb + kk + c * 8);
                }
            }
            asm volatile("cp.async.commit_group;" ::: "memory");
        };

        const int wm = (wid >> 1) * 32;
        const int wn = (wid & 1) * 128;

        float acc[16][4];
        #pragma unroll
        for (int jn = 0; jn < 16; jn++)
            #pragma unroll
            for (int q = 0; q < 4; q++) acc[jn][q] = 0.f;

        load_stage(0, 0);
        for (int kc = 0; kc < nChunks; kc++) {
            if (kc + 1 < nChunks) {
                load_stage((kc + 1) & 1, (kc + 1) * BK);
                asm volatile("cp.async.wait_group 1;" ::: "memory");
            } else {
                asm volatile("cp.async.wait_group 0;" ::: "memory");
            }
            __syncthreads();

            if (wid < 8) {
                uint32_t sb = sbase + (uint32_t)(kc & 1) * ST_SZ;
                #pragma unroll
                for (int k0 = 0; k0 < 64; k0 += 16) {
                    uint32_t a[2][2];
                    {
                        uint32_t r0a = sb + ST_A + (uint32_t)(wm + g) * 144 + (uint32_t)(k0 + tg * 2) * 2;
                        asm volatile("ld.shared.b32 %0, [%1];"        : "=r"(a[0][0]) : "r"(r0a));
                        asm volatile("ld.shared.b32 %0, [%1 + 1152];" : "=r"(a[0][1]) : "r"(r0a));
                        asm volatile("ld.shared.b32 %0, [%1 + 16];"   : "=r"(a[1][0]) : "r"(r0a));
                        asm volatile("ld.shared.b32 %0, [%1 + 1168];" : "=r"(a[1][1]) : "r"(r0a));
                    }
                    #pragma unroll
                    for (int jn = 0; jn < 16; jn++) {
                        uint32_t b0, b1;
                        uint32_t rb = sb + ST_B + (uint32_t)(wn + jn * 8 + g) * 144 + (uint32_t)(k0 + tg * 2) * 2;
                        asm volatile("ld.shared.b32 %0, [%1];"      : "=r"(b0) : "r"(rb));
                        asm volatile("ld.shared.b32 %0, [%1 + 16];" : "=r"(b1) : "r"(rb));
                        asm volatile(
                            "mma.sync.aligned.m16n8k16.row.col.f32.f16.f16.f32 "
                            "{%0,%1,%2,%3}, {%4,%5,%6,%7}, {%8,%9}, {%0,%1,%2,%3};"
                            : "+f"(acc[jn][0]), "+f"(acc[jn][1]),
                              "+f"(acc[jn][2]), "+f"(acc[jn][3])
                            : "r"(a[0][0]), "r"(a[0][1]), "r"(a[1][0]), "r"(a[1][1]),
                              "r"(b0), "r"(b1));
                    }
                }
            }
            __syncthreads();
        }

        if (wid < 8) {
            const long long r0w = (long long)m0h + wm + g;
            #pragma unroll
            for (int jn = 0; jn < 16; jn++) {
                const long long cc = (long long)n0h + wn + jn * 8 + tg * 2;
                if (OUT_HALF) {
                    __half* C = (__half*)Cv + blockIdx.z * sC;
                    *(__half2*)(C + r0w * ldc + cc)       = __floats2half2_rn(acc[jn][0], acc[jn][1]);
                    *(__half2*)(C + (r0w + 8) * ldc + cc) = __floats2half2_rn(acc[jn][2], acc[jn][3]);
                } else {
                    float* C = (float*)Cv + blockIdx.z * sC;
                    float* p0 = C + r0w * ldc + cc;
                    float* p1 = C + (r0w + 8) * ldc + cc;
                    p0[0] = acc[jn][0]; p0[1] = acc[jn][1];
                    p1[0] = acc[jn][2]; p1[1] = acc[jn][3];
                }
            }
        }
        __syncthreads();
    }
#endif
}

// ================= elementwise kernels =================
__device__ __forceinline__ uint32_t h2bits(__half2 h) { return *reinterpret_cast<uint32_t*>(&h); }

__global__ void cvt_f32_f16(const float* __restrict__ in, __half* __restrict__ out, int n8) {
    int i = blockIdx.x * 256 + threadIdx.x;
    if (i < n8) {
        float4 a = ((const float4*)in)[2*i], b = ((const float4*)in)[2*i+1];
        uint4 o;
        o.x = h2bits(__floats2half2_rn(a.x, a.y));
        o.y = h2bits(__floats2half2_rn(a.z, a.w));
        o.z = h2bits(__floats2half2_rn(b.x, b.y));
        o.w = h2bits(__floats2half2_rn(b.z, b.w));
        ((uint4*)out)[i] = o;
    }
}

__global__ void cvt_weights6(const float* s0, const float* s1, const float* s2,
                             const float* s3, const float* s4, const float* s5,
                             __half* d0, __half* d1, __half* d2,
                             __half* d3, __half* d4, __half* d5) {
    int i = blockIdx.x * 256 + threadIdx.x;
    int w = i >> 17;
    int j = i & 131071;
    const float* s; __half* d;
    switch (w) {
        case 0: s = s0; d = d0; break;
        case 1: s = s1; d = d1; break;
        case 2: s = s2; d = d2; break;
        case 3: s = s3; d = d3; break;
        case 4: s = s4; d = d4; break;
        default: s = s5; d = d5; break;
    }
    const float sc = (w == 1 || w == 4) ? QSCALE : 1.0f;
    float4 a = ((const float4*)s)[2*j], b = ((const float4*)s)[2*j+1];
    uint4 o;
    o.x = h2bits(__floats2half2_rn(a.x * sc, a.y * sc));
    o.y = h2bits(__floats2half2_rn(a.z * sc, a.w * sc));
    o.z = h2bits(__floats2half2_rn(b.x * sc, b.y * sc));
    o.w = h2bits(__floats2half2_rn(b.z * sc, b.w * sc));
    ((uint4*)d)[j] = o;
}

__global__ void copy_cache(const float* __restrict__ src, float* __restrict__ dstF,
                           __half* __restrict__ dstH, int hcol) {
    int row = blockIdx.x; int b = row / PAST, r = row % PAST;
    const float4* s  = (const float4*)(src + (size_t)row * 1024);
    float4* dF = (float4*)(dstF + ((size_t)b * STOT + r) * 1024);
    __half* dH = dstH + ((size_t)b * STOT + r) * 2048 + hcol;
    int j = threadIdx.x;
    float4 v = s[j];
    dF[j] = v;
    uint2 u; u.x = h2bits(__floats2half2_rn(v.x, v.y)); u.y = h2bits(__floats2half2_rn(v.z, v.w));
    *(uint2*)(dH + j * 4) = u;
}

__device__ __forceinline__ float blk_sum(float v, float* red) {
    const int tid = threadIdx.x;
    #pragma unroll
    for (int o = 16; o > 0; o >>= 1) v += __shfl_xor_sync(0xffffffffu, v, o);
    if ((tid & 31) == 0) red[tid >> 5] = v;
    __syncthreads();
    float t = (tid < 8) ? red[tid] : 0.f;
    if (tid < 32) {
        #pragma unroll
        for (int o = 4; o > 0; o >>= 1) t += __shfl_xor_sync(0xffffffffu, t, o);
        if (tid == 0) red[0] = t;
    }
    __syncthreads();
    float r = red[0];
    __syncthreads();
    return r;
}

__device__ __forceinline__ float blk_max(float v, float* red) {
    const int tid = threadIdx.x;
    #pragma unroll
    for (int o = 16; o > 0; o >>= 1) v = fmaxf(v, __shfl_xor_sync(0xffffffffu, v, o));
    if ((tid & 31) == 0) red[tid >> 5] = v;
    __syncthreads();
    float t = (tid < 8) ? red[tid] : -3.4e38f;
    if (tid < 32) {
        #pragma unroll
        for (int o = 4; o > 0; o >>= 1) t = fmaxf(t, __shfl_xor_sync(0xffffffffu, t, o));
        if (tid == 0) red[0] = t;
    }
    __syncthreads();
    float r = red[0];
    __syncthreads();
    return r;
}

__global__ void layernorm_kernel(const float* __restrict__ c, float* __restrict__ ckv,
                                 __half* __restrict__ kcat,
                                 const float* __restrict__ g, const float* __restrict__ b) {
    const int row = blockIdx.x; const int bb = row / SEQ, si = row % SEQ;
    const float* p = c + (size_t)row * LDIM;
    float*  o  = ckv  + ((size_t)bb * STOT + PAST + si) * 1024;
    __half* oh = kcat + ((size_t)bb * STOT + PAST + si) * 2048;
    __shared__ float red[8];
    const int tid = threadIdx.x;
    float s = 0.f, s2 = 0.f;
    for (int j = tid; j < LDIM; j += 256) { float v = p[j]; s += v; s2 += v * v; }
    s  = blk_sum(s,  red);
    s2 = blk_sum(s2, red);
    const float mean = s * (1.f / LDIM);
    const float var  = fmaxf(s2 * (1.f / LDIM) - mean * mean, 0.f);
    const float inv  = rsqrtf(var + 1e-5f);
    for (int j = tid; j < LDIM; j += 256) {
        float v = (p[j] - mean) * inv * g[j] + b[j];
        o[j] = v; oh[j] = __float2half_rn(v);
    }
}

__global__ void rope_k_kernel(const __half* __restrict__ in, float* __restrict__ kr,
                              __half* __restrict__ kcat) {
    const int row = blockIdx.x; const int bb = row / SEQ, t = row % SEQ;
    const int j = threadIdx.x;
    const __half* pi = in + (size_t)row * 1024;
    float*  po = kr   + ((size_t)bb * STOT + PAST + t) * 1024;
    __half* ph = kcat + ((size_t)bb * STOT + PAST + t) * 2048 + 1024;
    float x1 = __half2float(pi[j]), x2 = __half2float(pi[j + 512]);
    const float inv_freq = powf(10000.f, -(float)(2 * j) * (1.f / 1024.f));
    float sn, cs; sincosf((float)t * inv_freq, &sn, &cs);
    float y1 = x1 * cs - x2 * sn, y2 = x2 * cs + x1 * sn;
    po[j] = y1; po[j + 512] = y2;
    ph[j] = __float2half_rn(y1); ph[j + 512] = __float2half_rn(y2);
}

__global__ void rope_q_kernel(const __half* __restrict__ in, __half* __restrict__ qcat,
                              const float* __restrict__ bias) {
    const int row = blockIdx.x; const int t = row % SEQ;
    const int j = threadIdx.x;
    const __half* pi = in + (size_t)row * 1024;
    __half* ph = qcat + (size_t)row * 2048 + 1024;
    float x1 = __half2float(pi[j]) + QSCALE * bias[j];
    float x2 = __half2float(pi[j + 512]) + QSCALE * bias[j + 512];
    const float inv_freq = powf(10000.f, -(float)(2 * j) * (1.f / 1024.f));
    float sn, cs; sincosf((float)t * inv_freq, &sn, &cs);
    ph[j]       = __float2half_rn(x1 * cs - x2 * sn);
    ph[j + 512] = __float2half_rn(x2 * cs + x1 * sn);
}

__global__ void softmax_kernel(const float* __restrict__ sc, __half* __restrict__ wh) {
    const int row = blockIdx.x;
    const int si  = row % SEQ;
    const int valid = si + PAST + 1;
    const float* p = sc + (size_t)row * STOT;
    __half* o = wh + (size_t)row * STOT;
    __shared__ float buf[STOT];
    __shared__ float red[8];
    const int tid = threadIdx.x;

    float mx = -3.4e38f;
    for (int j = tid; j < valid; j += 256) { float v = p[j]; buf[j] = v; mx = fmaxf(mx, v); }
    mx = blk_max(mx, red);
    float sum = 0.f;
    for (int j = tid; j < valid; j += 256) { float e = __expf(buf[j] - mx); buf[j] = e; sum += e; }
    sum = blk_sum(sum, red);
    const float inv = 1.f / sum;
    for (int j = tid; j < valid; j += 256) o[j] = __float2half_rn(buf[j] * inv);
    for (int j = valid + tid; j < STOT; j += 256) o[j] = __float2half_rn(0.f);
}

// ================= launch =================
extern "C" void kernel_launch(void* const* d_in, const int* in_sizes, int n_in,
                              void* d_out, int out_size)
{
    (void)in_sizes; (void)n_in; (void)out_size;
    const float* x        = (const float*)d_in[0];
    const float* kv_cache = (const float*)d_in[1];
    const float* kr_cache = (const float*)d_in[2];
    const float* Wq       = (const float*)d_in[3];
    const float* Wdkv     = (const float*)d_in[4];
    const float* Wuk      = (const float*)d_in[5];
    const float* Wuv      = (const float*)d_in[6];
    const float* Wo       = (const float*)d_in[7];
    const float* Wkr      = (const float*)d_in[8];
    const float* Wqr      = (const float*)d_in[9];
    const float* bqr      = (const float*)d_in[10];
    const float* ln_g     = (const float*)d_in[11];
    const float* ln_b     = (const float*)d_in[12];

    float* out = (float*)d_out;
    float* ckv = out + (size_t)B_ * SEQ * EDIM;
    float* kr  = ckv + (size_t)B_ * STOT * LDIM;

    __half *xh, *wqh, *wukh, *wdkvh, *wkrh, *wqrh, *woh, *wuvh, *wuvwoT, *absTh, *Kcat, *Qcat, *wh, *vTh;
    __half *krp, *qpre;
    float *c, *sc;
    cudaGetSymbolAddress((void**)&xh,     g_xh);
    cudaGetSymbolAddress((void**)&wqh,    g_Wqh);
    cudaGetSymbolAddress((void**)&wukh,   g_Wukh);
    cudaGetSymbolAddress((void**)&wdkvh,  g_Wdkvh);
    cudaGetSymbolAddress((void**)&wkrh,   g_Wkrh);
    cudaGetSymbolAddress((void**)&wqrh,   g_Wqrh);
    cudaGetSymbolAddress((void**)&woh,    g_Woh);
    cudaGetSymbolAddress((void**)&wuvh,   g_Wuvh);
    cudaGetSymbolAddress((void**)&wuvwoT, g_WuvWoT);
    cudaGetSymbolAddress((void**)&absTh,  g_absTh);
    cudaGetSymbolAddress((void**)&c,      g_c);
    cudaGetSymbolAddress((void**)&krp,    g_krp);
    cudaGetSymbolAddress((void**)&qpre,   g_qpre);
    cudaGetSymbolAddress((void**)&Kcat,   g_Kcat);
    cudaGetSymbolAddress((void**)&Qcat,   g_Qcat);
    cudaGetSymbolAddress((void**)&sc,     g_sc);
    cudaGetSymbolAddress((void**)&wh,     g_wh);
    cudaGetSymbolAddress((void**)&vTh,    g_vTh);

    cudaFuncSetAttribute(hgemm<false>, cudaFuncAttributeMaxDynamicSharedMemorySize, GEMM_SMEM);
    cudaFuncSetAttribute(hgemm<true>,  cudaFuncAttributeMaxDynamicSharedMemorySize, GEMM_SMEM);

    // ---- proven topology: 3 streams, 9 events, single-use ----
    static cudaStream_t st[3] = {nullptr, nullptr, nullptr};
    static cudaEvent_t  ev[10] = {};
    if (st[0] == nullptr) {
        for (int i = 0; i < 3; i++) cudaStreamCreateWithFlags(&st[i], cudaStreamNonBlocking);
        for (int i = 0; i < 10; i++) cudaEventCreateWithFlags(&ev[i], cudaEventDisableTiming);
    }
    cudaEvent_t eFork = ev[0], eX = ev[1], eW = ev[2], eXa = ev[3], eT = ev[4],
                eRk = ev[5], eCc = ev[6], eLN = ev[7], eV = ev[8];

    const long long sL2 = (long long)SEQ * 2048;
    const long long SL2 = (long long)STOT * 2048;
    const long long sS  = (long long)SEQ * STOT;
    const long long sE  = (long long)SEQ * 1024;
    const long long ES  = (long long)EDIM * STOT;

    // ---------------- FORK ----------------
    cudaEventRecord(eFork, 0);
    for (int i = 0; i < 3; i++) cudaStreamWaitEvent(st[i], eFork, 0);

    cvt_f32_f16<<<4096, 256>>>(x, xh, (B_*SEQ*EDIM)/8);
    cudaEventRecord(eX, 0);

    // st[0]: weights cvt -> absT -> xa (Qcat left)
    cvt_weights6<<<3072, 256, 0, st[0]>>>(Wq, Wuk, Wdkv, Wkr, Wqr, Wo,
                                          wqh, wukh, wdkvh, wkrh, wqrh, woh);
    cudaEventRecord(eW, st[0]);
    hgemm<true><<<dim3(4, 4, 1), GEMM_THREADS, GEMM_SMEM, st[0]>>>(
        wukh, wqh, absTh, 1024, 1024, 1024, 0, 0, 0, 1024, 1024, 1024, 0);
    cudaStreamWaitEvent(st[0], eX, 0);
    hgemm<true><<<dim3(4, 32, 1), GEMM_THREADS, GEMM_SMEM, st[0]>>>(
        xh, absTh, Qcat, 8192, 1024, 1024, 0, 0, 0, 1024, 1024, 2048, 0);
    cudaEventRecord(eXa, st[0]);

    // st[1]: Wuv cvt -> WuvWoT = Wo @ Wuv^T, then krp (fp16) -> rope_k
    cvt_f32_f16<<<512, 256, 0, st[1]>>>(Wuv, wuvh, (LDIM*EDIM)/8);
    cudaStreamWaitEvent(st[1], eW, 0);
    hgemm<true><<<dim3(4, 4, 1), GEMM_THREADS, GEMM_SMEM, st[1]>>>(
        woh, wuvh, wuvwoT, 1024, 1024, 1024, 0, 0, 0, 1024, 1024, 1024, 0);
    cudaEventRecord(eT, st[1]);
    cudaStreamWaitEvent(st[1], eX, 0);
    hgemm<true><<<dim3(4, 32, 1), GEMM_THREADS, GEMM_SMEM, st[1]>>>(
        xh, wkrh, krp, 8192, 1024, 1024, 0, 0, 0, 1024, 1024, 1024, 0);
    rope_k_kernel<<<B_*SEQ, 512, 0, st[1]>>>(krp, kr, Kcat);
    cudaEventRecord(eRk, st[1]);

    // st[2]: cache copies
    copy_cache<<<B_*PAST, 256, 0, st[2]>>>(kv_cache, ckv, Kcat, 0);
    copy_cache<<<B_*PAST, 256, 0, st[2]>>>(kr_cache, kr,  Kcat, 1024);
    cudaEventRecord(eCc, st[2]);

    // main: c -> LN -> qpre (fp16) -> rope_q (critical path)
    cudaStreamWaitEvent(0, eW, 0);
    hgemm<false><<<dim3(4, 32, 1), GEMM_THREADS, GEMM_SMEM>>>(
        xh, wdkvh, c, 8192, 1024, 1024, 0, 0, 0, 1024, 1024, 1024, 0);
    layernorm_kernel<<<B_*SEQ, 256>>>(c, ckv, Kcat, ln_g, ln_b);
    cudaEventRecord(eLN, 0);
    hgemm<true><<<dim3(4, 8, 4), GEMM_THREADS, GEMM_SMEM>>>(
        Kcat + (size_t)PAST * 2048, wqrh, qpre, 2048, 1024, 1024,
        SL2, 0, sE, 2048, 1024, 1024, 0);
    rope_q_kernel<<<B_*SEQ, 512>>>(qpre, Qcat, bqr);

    // st[2]: valueWT[E,S] = WuvWoT @ ckv^T (folded Wo) — overlaps scores+softmax
    cudaStreamWaitEvent(st[2], eLN, 0);
    cudaStreamWaitEvent(st[2], eT, 0);
    hgemm<true><<<dim3(16, 4, 4), GEMM_THREADS, GEMM_SMEM, st[2]>>>(
        wuvwoT, Kcat, vTh, 1024, 4096, 1024, 0, SL2, ES, 1024, 2048, 4096, 0);
    cudaEventRecord(eV, st[2]);

    // ---------------- JOIN for scores ----------------
    cudaStreamWaitEvent(0, eXa, 0);
    cudaStreamWaitEvent(0, eRk, 0);
    cudaStreamWaitEvent(0, eCc, 0);

    // scores = Qcat @ Kcat^T (pre-scaled; K=2048; causal tile skip)
    hgemm<false><<<dim3(16, 8, 4), GEMM_THREADS, GEMM_SMEM>>>(
        Qcat, Kcat, sc, 2048, 4096, 2048, sL2, SL2, sS, 2048, 2048, 4096, 1);

    softmax_kernel<<<B_*SEQ, 256>>>(sc, wh);

    // out = w @ valueWT^T  (fp32 directly to d_out; causal K-limit)
    cudaStreamWaitEvent(0, eV, 0);
    hgemm<false><<<dim3(4, 8, 4), GEMM_THREADS, GEMM_SMEM>>>(
        wh, vTh, out, 2048, 1024, 4096, sS, ES, sE, 4096, 4096, 1024, 2);
}

// round 17
// speedup vs baseline: 1.1185x; 1.0315x over previous
#include <cuda_runtime.h>
#include <cuda_fp16.h>
#include <math.h>
#include <stdint.h>

// ---------------- fixed problem shapes ----------------
#define B_    4
#define SEQ   2048
#define PAST  2048
#define EDIM  1024
#define LDIM  1024
#define STOT  4096
#define QSCALE 0.022097086912079608f   // 1/sqrt(2*LDIM)

// ---------------- scratch (device globals) ----------------
__device__ __align__(256) __half g_xh    [(size_t)B_*SEQ*EDIM];
__device__ __align__(256) __half g_Wqh   [EDIM*EDIM];
__device__ __align__(256) __half g_Wukh  [LDIM*EDIM];
__device__ __align__(256) __half g_Wdkvh [LDIM*EDIM];
__device__ __align__(256) __half g_Wkrh  [LDIM*EDIM];
__device__ __align__(256) __half g_Wqrh  [EDIM*LDIM];
__device__ __align__(256) __half g_Woh   [EDIM*EDIM];
__device__ __align__(256) __half g_Wuvh  [LDIM*EDIM];
__device__ __align__(256) __half g_WuvWoT[EDIM*LDIM];   // Wo @ Wuv^T
__device__ __align__(256) __half g_absTh [LDIM*EDIM];
__device__ __align__(256) __half g_c     [(size_t)B_*SEQ*LDIM];  // fp16 now
__device__ __align__(256) __half g_krp   [(size_t)B_*SEQ*LDIM];
__device__ __align__(256) __half g_qpre  [(size_t)B_*SEQ*EDIM];
__device__ __align__(256) __half g_Kcat  [(size_t)B_*STOT*2048];  // [ckv | kr] fp16
__device__ __align__(256) __half g_Qcat  [(size_t)B_*SEQ*2048];   // [xa | q_r] fp16
__device__ __align__(256) float  g_sc    [(size_t)B_*SEQ*STOT];
__device__ __align__(256) __half g_wh    [(size_t)B_*SEQ*STOT];
__device__ __align__(256) __half g_vTh   [(size_t)B_*EDIM*STOT];  // (value@Wo^T)^T per batch [E,S]

// ================= GEMM config (R9/R14/R15 best) =================
#define BM 256
#define BN 512
#define BK 64
#define NSTG 4
#define STAGE_BYTES 49152
#define GEMM_THREADS 288
#define GEMM_SMEM (NSTG*STAGE_BYTES + 1024 + 128)

#if defined(__CUDA_ARCH__) && (defined(__CUDA_ARCH_FEAT_SM103_ALL) || defined(__CUDA_ARCH_FEAT_SM100_ALL) || defined(__CUDA_ARCH_FEAT_SM101_ALL))
#define USE_TCGEN05 1
#else
#define USE_TCGEN05 0
#endif

__device__ __forceinline__ void cp_async16(uint32_t dst, const void* src) {
    asm volatile("cp.async.cg.shared.global [%0], [%1], 16;" :: "r"(dst), "l"(src) : "memory");
}

#if USE_TCGEN05
__device__ __forceinline__ uint32_t sw128(uint32_t o) { return o ^ ((o >> 3) & 0x70u); }

__device__ __forceinline__ uint64_t make_desc(uint32_t addr) {
    return ((uint64_t)2 << 61) | (1ull << 46) | (64ull << 32) | (1ull << 16)
         | ((addr >> 4) & 0x3FFFull);
}

__device__ __forceinline__ bool elect_one() {
    uint32_t pred;
    asm volatile("{\n\t.reg .pred p;\n\telect.sync _|p, 0xFFFFFFFF;\n\tselp.b32 %0, 1, 0, p;\n\t}"
                 : "=r"(pred));
    return pred != 0;
}

__device__ __forceinline__ void mbar_init(uint32_t a, uint32_t cnt) {
    asm volatile("mbarrier.init.shared.b64 [%0], %1;" :: "r"(a), "r"(cnt) : "memory");
}

__device__ __forceinline__ void mbar_wait(uint32_t a, uint32_t ph) {
    asm volatile(
        "{\n\t.reg .pred P;\n"
        "LW%=:\n\t"
        "mbarrier.try_wait.parity.acquire.cta.shared::cta.b64 P, [%0], %1, 0x989680;\n\t"
        "@!P bra LW%=;\n\t}"
        :: "r"(a), "r"(ph) : "memory");
}

__device__ __forceinline__ void cp_async_arrive(uint32_t bar) {
    asm volatile("cp.async.mbarrier.arrive.noinc.shared::cta.b64 [%0];" :: "r"(bar) : "memory");
}

__device__ __forceinline__ void mbar_arrive_leader(uint32_t local_addr) {
    asm volatile(
        "{\n\t.reg .b32 remAddr;\n\t"
        "mapa.shared::cluster.u32 remAddr, %0, 0;\n\t"
        "mbarrier.arrive.shared::cluster.b64 _, [remAddr];\n\t}"
        :: "r"(local_addr) : "memory");
}

__device__ __forceinline__ void mma_f16_cg2(uint32_t d, uint64_t ad, uint64_t bd,
                                            uint32_t idesc, uint32_t en) {
    asm volatile(
        "{\n\t.reg .pred p;\n\tsetp.ne.u32 p, %4, 0;\n\t"
        "tcgen05.mma.cta_group::2.kind::f16 [%0], %1, %2, %3, "
        "{%5, %5, %5, %5, %5, %5, %5, %5}, p;\n\t}"
        :: "r"(d), "l"(ad), "l"(bd), "r"(idesc), "r"(en), "r"(0u) : "memory");
}

__device__ __forceinline__ void tc_commit_mc2(uint32_t bar) {
    asm volatile(
        "tcgen05.commit.cta_group::2.mbarrier::arrive::one.shared::cluster.multicast::cluster.b64 [%0], %1;"
        :: "r"(bar), "h"((uint16_t)3) : "memory");
}

__device__ __forceinline__ void ldtm32(uint32_t* r, uint32_t addr) {
    asm volatile(
        "tcgen05.ld.sync.aligned.32x32b.x32.b32 "
        "{%0, %1, %2, %3, %4, %5, %6, %7, "
        " %8, %9, %10, %11, %12, %13, %14, %15, "
        " %16, %17, %18, %19, %20, %21, %22, %23, "
        " %24, %25, %26, %27, %28, %29, %30, %31}, [%32];"
        : "=r"(r[0]),  "=r"(r[1]),  "=r"(r[2]),  "=r"(r[3]),
          "=r"(r[4]),  "=r"(r[5]),  "=r"(r[6]),  "=r"(r[7]),
          "=r"(r[8]),  "=r"(r[9]),  "=r"(r[10]), "=r"(r[11]),
          "=r"(r[12]), "=r"(r[13]), "=r"(r[14]), "=r"(r[15]),
          "=r"(r[16]), "=r"(r[17]), "=r"(r[18]), "=r"(r[19]),
          "=r"(r[20]), "=r"(r[21]), "=r"(r[22]), "=r"(r[23]),
          "=r"(r[24]), "=r"(r[25]), "=r"(r[26]), "=r"(r[27]),
          "=r"(r[28]), "=r"(r[29]), "=r"(r[30]), "=r"(r[31])
        : "r"(addr));
}
#endif  // USE_TCGEN05

// C[M,N] = A[M,K] * B[N,K]^T, fp16 in, fp32 accum. M%256==0, N%512==0, K%64==0.
// 2-CTA cluster pair per (m,n) tile. cflag bit0: causal tile skip; bit1: causal K-limit.
template<bool OUT_HALF>
__global__ void __launch_bounds__(GEMM_THREADS, 1) __cluster_dims__(2, 1, 1)
hgemm(const __half* __restrict__ A, const __half* __restrict__ Bm, void* __restrict__ Cv,
      int M, int N, int K, long long sA, long long sB, long long sC,
      int lda, int ldb, int ldc, int cflag)
{
    extern __shared__ char dynsmem[];
    const int tid  = threadIdx.x;
    const int wid  = tid >> 5;
    const int rank = blockIdx.x & 1;
    const int m0 = blockIdx.y * BM;
    const int n0 = (blockIdx.x >> 1) * BN;
    if ((cflag & 1) && n0 >= m0 + BM + PAST) return;

    int nChunks = K >> 6;
    if (cflag & 2) {
        int lim = (m0 + BM + PAST) >> 6;
        if (lim < nChunks) nChunks = lim;
    }

    A  += (long long)blockIdx.z * sA;
    Bm += (long long)blockIdx.z * sB;

#if USE_TCGEN05
    uint32_t raw  = (uint32_t)__cvta_generic_to_shared(dynsmem);
    uint32_t tb   = (raw + 1023u) & ~1023u;
    uint32_t ctrl = tb + NSTG * STAGE_BYTES;

    if (tid == 0) {
        #pragma unroll
        for (int s = 0; s < NSTG; s++) {
            mbar_init(ctrl + 8  + 8*s, (rank == 0) ? 257u : 256u);
            mbar_init(ctrl + 40 + 8*s, 1);
        }
        mbar_init(ctrl + 72, 1);
    }
    __syncthreads();
    if (wid == 8) {
        asm volatile("tcgen05.alloc.cta_group::2.sync.aligned.shared::cta.b32 [%0], %1;"
                     :: "r"(ctrl), "r"(512u) : "memory");
        asm volatile("tcgen05.relinquish_alloc_permit.cta_group::2.sync.aligned;");
    }
    __syncthreads();
    asm volatile("barrier.cluster.arrive.aligned;" ::: "memory");
    asm volatile("barrier.cluster.wait.aligned;"   ::: "memory");

    uint32_t tmem;
    asm volatile("ld.shared.b32 %0, [%1];" : "=r"(tmem) : "r"(ctrl));

    if (wid < 8) {
        const int r0  = tid >> 3;
        const int c16 = tid & 7;
        uint32_t sw[4];
        #pragma unroll
        for (int i = 0; i < 4; i++) sw[i] = sw128((uint32_t)((r0 + 32*i) * 128 + c16 * 16));
        const __half* ap  = A  + (long long)(m0 + rank*128 + r0)        * lda + c16 * 8;
        const __half* b0p = Bm + (long long)(n0 + rank*128 + r0)        * ldb + c16 * 8;
        const __half* b1p = Bm + (long long)(n0 + 256 + rank*128 + r0)  * ldb + c16 * 8;
        const long long la32 = (long long)lda * 32, lb32 = (long long)ldb * 32;

        uint32_t ph = 1; int s = 0;
        for (int kc = 0; kc < nChunks; kc++) {
            mbar_wait(ctrl + 40 + 8*s, ph);
            uint32_t sb = tb + s * STAGE_BYTES;
            #pragma unroll
            for (int i = 0; i < 4; i++) cp_async16(sb + sw[i],          ap  + i * la32);
            #pragma unroll
            for (int i = 0; i < 4; i++) cp_async16(sb + 16384u + sw[i], b0p + i * lb32);
            #pragma unroll
            for (int i = 0; i < 4; i++) cp_async16(sb + 32768u + sw[i], b1p + i * lb32);
            cp_async_arrive(ctrl + 8 + 8*s);
            ap += BK; b0p += BK; b1p += BK;
            if (++s == NSTG) { s = 0; ph ^= 1; }
        }

        mbar_wait(ctrl + 72, 0);
        asm volatile("tcgen05.fence::after_thread_sync;" ::: "memory");
        const int l = tid & 31;
        const int half = wid >> 2;
        const uint32_t dtm = tmem + half * 256u;
        const long long row = (long long)m0 + rank * 128 + (wid & 3) * 32 + l;
        const int colbase = n0 + half * 256;
        if (OUT_HALF) {
            __half* C = (__half*)Cv + blockIdx.z * sC + row * ldc + colbase;
            for (int b8 = 0; b8 < 8; b8++) {
                uint32_t r[32];
                ldtm32(r, dtm + b8 * 32);
                asm volatile("tcgen05.wait::ld.sync.aligned;" ::: "memory");
                uint32_t h[16];
                #pragma unroll
                for (int j = 0; j < 16; j++) {
                    __half2 hv = __floats2half2_rn(__uint_as_float(r[2*j]), __uint_as_float(r[2*j+1]));
                    h[j] = *reinterpret_cast<uint32_t*>(&hv);
                }
                uint4* dst = (uint4*)(C + b8 * 32);
                #pragma unroll
                for (int q = 0; q < 4; q++) dst[q] = make_uint4(h[4*q], h[4*q+1], h[4*q+2], h[4*q+3]);
            }
        } else {
            float* C = (float*)Cv + blockIdx.z * sC + row * ldc + colbase;
            for (int b8 = 0; b8 < 8; b8++) {
                uint32_t r[32];
                ldtm32(r, dtm + b8 * 32);
                asm volatile("tcgen05.wait::ld.sync.aligned;" ::: "memory");
                float4* dst = (float4*)(C + b8 * 32);
                #pragma unroll
                for (int q = 0; q < 8; q++)
                    dst[q] = make_float4(__uint_as_float(r[4*q]),   __uint_as_float(r[4*q+1]),
                                         __uint_as_float(r[4*q+2]), __uint_as_float(r[4*q+3]));
            }
        }
    } else if (rank == 0) {
        const uint32_t idesc = (1u << 4) | (32u << 17) | (16u << 24);
        uint32_t ph = 0; int s = 0;
        for (int kc = 0; kc < nChunks; kc++) {
            mbar_wait(ctrl + 8 + 8*s, ph);
            if (elect_one()) {
                asm volatile("fence.proxy.async.shared::cta;" ::: "memory");
                uint64_t ad = make_desc(tb + s * STAGE_BYTES);
                uint64_t b0 = make_desc(tb + s * STAGE_BYTES + 16384);
                uint64_t b1 = make_desc(tb + s * STAGE_BYTES + 32768);
                #pragma unroll
                for (int st = 0; st < 4; st++) {
                    uint32_t en = (kc == 0 && st == 0) ? 0u : 1u;
                    mma_f16_cg2(tmem,       ad + st * 2, b0 + st * 2, idesc, en);
                    mma_f16_cg2(tmem + 256, ad + st * 2, b1 + st * 2, idesc, en);
                }
                tc_commit_mc2(ctrl + 40 + 8*s);
            }
            if (++s == NSTG) { s = 0; ph ^= 1; }
        }
        if (elect_one()) tc_commit_mc2(ctrl + 72);
    } else {
        uint32_t ph = 0; int s = 0;
        for (int kc = 0; kc < nChunks; kc++) {
            mbar_wait(ctrl + 8 + 8*s, ph);
            if (elect_one()) mbar_arrive_leader(ctrl + 8 + 8*s);
            if (++s == NSTG) { s = 0; ph ^= 1; }
        }
    }

    __syncthreads();
    if (wid == 8)
        asm volatile("tcgen05.dealloc.cta_group::2.sync.aligned.b32 %0, %1;" :: "r"(tmem), "r"(512u));
    asm volatile("barrier.cluster.arrive.aligned;" ::: "memory");
    asm volatile("barrier.cluster.wait.aligned;"   ::: "memory");

#else
    // ===================== mma.sync fallback (plain sm_103) =====================
    const int lane = tid & 31;
    const int g  = lane >> 2;
    const int tg = lane & 3;
    uint32_t sbase = (uint32_t)__cvta_generic_to_shared(dynsmem);
    sbase = (sbase + 127u) & ~127u;
    const uint32_t ST_A = 0, ST_B = 128 * 144, ST_SZ = 128 * 144 + 256 * 144;
    const int m0h = m0 + rank * 128;

    for (int nh = 0; nh < 2; nh++) {
        const int n0h = n0 + nh * 256;

        auto load_stage = [&](int s, int kk) {
            uint32_t sb = sbase + (uint32_t)s * ST_SZ;
            for (int idx = tid; idx < 3072; idx += GEMM_THREADS) {
                if (idx < 1024) {
                    int row = idx >> 3, c = idx & 7;
                    cp_async16(sb + ST_A + row * 144 + c * 16,
                               A + (long long)(m0h + row) * lda + kk + c * 8);
                } else {
                    int j = idx - 1024;
                    int row = j >> 3, c = j & 7;
                    cp_async16(sb + ST_B + row * 144 + c * 16,
                               Bm + (long long)(n0h + row) * ldb + kk + c * 8);
                }
            }
            asm volatile("cp.async.commit_group;" ::: "memory");
        };

        const int wm = (wid >> 1) * 32;
        const int wn = (wid & 1) * 128;

        float acc[16][4];
        #pragma unroll
        for (int jn = 0; jn < 16; jn++)
            #pragma unroll
            for (int q = 0; q < 4; q++) acc[jn][q] = 0.f;

        load_stage(0, 0);
        for (int kc = 0; kc < nChunks; kc++) {
            if (kc + 1 < nChunks) {
                load_stage((kc + 1) & 1, (kc + 1) * BK);
                asm volatile("cp.async.wait_group 1;" ::: "memory");
            } else {
                asm volatile("cp.async.wait_group 0;" ::: "memory");
            }
            __syncthreads();

            if (wid < 8) {
                uint32_t sb = sbase + (uint32_t)(kc & 1) * ST_SZ;
                #pragma unroll
                for (int k0 = 0; k0 < 64; k0 += 16) {
                    uint32_t a[2][2];
                    {
                        uint32_t r0a = sb + ST_A + (uint32_t)(wm + g) * 144 + (uint32_t)(k0 + tg * 2) * 2;
                        asm volatile("ld.shared.b32 %0, [%1];"        : "=r"(a[0][0]) : "r"(r0a));
                        asm volatile("ld.shared.b32 %0, [%1 + 1152];" : "=r"(a[0][1]) : "r"(r0a));
                        asm volatile("ld.shared.b32 %0, [%1 + 16];"   : "=r"(a[1][0]) : "r"(r0a));
                        asm volatile("ld.shared.b32 %0, [%1 + 1168];" : "=r"(a[1][1]) : "r"(r0a));
                    }
                    #pragma unroll
                    for (int jn = 0; jn < 16; jn++) {
                        uint32_t b0, b1;
                        uint32_t rb = sb + ST_B + (uint32_t)(wn + jn * 8 + g) * 144 + (uint32_t)(k0 + tg * 2) * 2;
                        asm volatile("ld.shared.b32 %0, [%1];"      : "=r"(b0) : "r"(rb));
                        asm volatile("ld.shared.b32 %0, [%1 + 16];" : "=r"(b1) : "r"(rb));
                        asm volatile(
                            "mma.sync.aligned.m16n8k16.row.col.f32.f16.f16.f32 "
                            "{%0,%1,%2,%3}, {%4,%5,%6,%7}, {%8,%9}, {%0,%1,%2,%3};"
                            : "+f"(acc[jn][0]), "+f"(acc[jn][1]),
                              "+f"(acc[jn][2]), "+f"(acc[jn][3])
                            : "r"(a[0][0]), "r"(a[0][1]), "r"(a[1][0]), "r"(a[1][1]),
                              "r"(b0), "r"(b1));
                    }
                }
            }
            __syncthreads();
        }

        if (wid < 8) {
            const long long r0w = (long long)m0h + wm + g;
            #pragma unroll
            for (int jn = 0; jn < 16; jn++) {
                const long long cc = (long long)n0h + wn + jn * 8 + tg * 2;
                if (OUT_HALF) {
                    __half* C = (__half*)Cv + blockIdx.z * sC;
                    *(__half2*)(C + r0w * ldc + cc)       = __floats2half2_rn(acc[jn][0], acc[jn][1]);
                    *(__half2*)(C + (r0w + 8) * ldc + cc) = __floats2half2_rn(acc[jn][2], acc[jn][3]);
                } else {
                    float* C = (float*)Cv + blockIdx.z * sC;
                    float* p0 = C + r0w * ldc + cc;
                    float* p1 = C + (r0w + 8) * ldc + cc;
                    p0[0] = acc[jn][0]; p0[1] = acc[jn][1];
                    p1[0] = acc[jn][2]; p1[1] = acc[jn][3];
                }
            }
        }
        __syncthreads();
    }
#endif
}

// ================= elementwise kernels =================
__device__ __forceinline__ uint32_t h2bits(__half2 h) { return *reinterpret_cast<uint32_t*>(&h); }

__global__ void cvt_f32_f16(const float* __restrict__ in, __half* __restrict__ out, int n8) {
    int i = blockIdx.x * 256 + threadIdx.x;
    if (i < n8) {
        float4 a = ((const float4*)in)[2*i], b = ((const float4*)in)[2*i+1];
        uint4 o;
        o.x = h2bits(__floats2half2_rn(a.x, a.y));
        o.y = h2bits(__floats2half2_rn(a.z, a.w));
        o.z = h2bits(__floats2half2_rn(b.x, b.y));
        o.w = h2bits(__floats2half2_rn(b.z, b.w));
        ((uint4*)out)[i] = o;
    }
}

__global__ void cvt_weights6(const float* s0, const float* s1, const float* s2,
                             const float* s3, const float* s4, const float* s5,
                             __half* d0, __half* d1, __half* d2,
                             __half* d3, __half* d4, __half* d5) {
    int i = blockIdx.x * 256 + threadIdx.x;
    int w = i >> 17;
    int j = i & 131071;
    const float* s; __half* d;
    switch (w) {
        case 0: s = s0; d = d0; break;
        case 1: s = s1; d = d1; break;
        case 2: s = s2; d = d2; break;
        case 3: s = s3; d = d3; break;
        case 4: s = s4; d = d4; break;
        default: s = s5; d = d5; break;
    }
    const float sc = (w == 1 || w == 4) ? QSCALE : 1.0f;
    float4 a = ((const float4*)s)[2*j], b = ((const float4*)s)[2*j+1];
    uint4 o;
    o.x = h2bits(__floats2half2_rn(a.x * sc, a.y * sc));
    o.y = h2bits(__floats2half2_rn(a.z * sc, a.w * sc));
    o.z = h2bits(__floats2half2_rn(b.x * sc, b.y * sc));
    o.w = h2bits(__floats2half2_rn(b.z * sc, b.w * sc));
    ((uint4*)d)[j] = o;
}

__global__ void copy_cache(const float* __restrict__ src, float* __restrict__ dstF,
                           __half* __restrict__ dstH, int hcol) {
    int row = blockIdx.x; int b = row / PAST, r = row % PAST;
    const float4* s  = (const float4*)(src + (size_t)row * 1024);
    float4* dF = (float4*)(dstF + ((size_t)b * STOT + r) * 1024);
    __half* dH = dstH + ((size_t)b * STOT + r) * 2048 + hcol;
    int j = threadIdx.x;
    float4 v = s[j];
    dF[j] = v;
    uint2 u; u.x = h2bits(__floats2half2_rn(v.x, v.y)); u.y = h2bits(__floats2half2_rn(v.z, v.w));
    *(uint2*)(dH + j * 4) = u;
}

__device__ __forceinline__ float blk_sum(float v, float* red) {
    const int tid = threadIdx.x;
    #pragma unroll
    for (int o = 16; o > 0; o >>= 1) v += __shfl_xor_sync(0xffffffffu, v, o);
    if ((tid & 31) == 0) red[tid >> 5] = v;
    __syncthreads();
    float t = (tid < 8) ? red[tid] : 0.f;
    if (tid < 32) {
        #pragma unroll
        for (int o = 4; o > 0; o >>= 1) t += __shfl_xor_sync(0xffffffffu, t, o);
        if (tid == 0) red[0] = t;
    }
    __syncthreads();
    float r = red[0];
    __syncthreads();
    return r;
}

__device__ __forceinline__ float blk_max(float v, float* red) {
    const int tid = threadIdx.x;
    #pragma unroll
    for (int o = 16; o > 0; o >>= 1) v = fmaxf(v, __shfl_xor_sync(0xffffffffu, v, o));
    if ((tid & 31) == 0) red[tid >> 5] = v;
    __syncthreads();
    float t = (tid < 8) ? red[tid] : -3.4e38f;
    if (tid < 32) {
        #pragma unroll
        for (int o = 4; o > 0; o >>= 1) t = fmaxf(t, __shfl_xor_sync(0xffffffffu, t, o));
        if (tid == 0) red[0] = t;
    }
    __syncthreads();
    float r = red[0];
    __syncthreads();
    return r;
}

// layernorm over fp16 c row (fp32 accumulation) -> d_out ckv tail + Kcat left half
__global__ void layernorm_kernel(const __half* __restrict__ c, float* __restrict__ ckv,
                                 __half* __restrict__ kcat,
                                 const float* __restrict__ g, const float* __restrict__ b) {
    const int row = blockIdx.x; const int bb = row / SEQ, si = row % SEQ;
    const __half* p = c + (size_t)row * LDIM;
    float*  o  = ckv  + ((size_t)bb * STOT + PAST + si) * 1024;
    __half* oh = kcat + ((size_t)bb * STOT + PAST + si) * 2048;
    __shared__ float red[8];
    const int tid = threadIdx.x;
    float s = 0.f, s2 = 0.f;
    for (int j = tid; j < LDIM; j += 256) { float v = __half2float(p[j]); s += v; s2 += v * v; }
    s  = blk_sum(s,  red);
    s2 = blk_sum(s2, red);
    const float mean = s * (1.f / LDIM);
    const float var  = fmaxf(s2 * (1.f / LDIM) - mean * mean, 0.f);
    const float inv  = rsqrtf(var + 1e-5f);
    for (int j = tid; j < LDIM; j += 256) {
        float v = (__half2float(p[j]) - mean) * inv * g[j] + b[j];
        o[j] = v; oh[j] = __float2half_rn(v);
    }
}

__global__ void rope_k_kernel(const __half* __restrict__ in, float* __restrict__ kr,
                              __half* __restrict__ kcat) {
    const int row = blockIdx.x; const int bb = row / SEQ, t = row % SEQ;
    const int j = threadIdx.x;
    const __half* pi = in + (size_t)row * 1024;
    float*  po = kr   + ((size_t)bb * STOT + PAST + t) * 1024;
    __half* ph = kcat + ((size_t)bb * STOT + PAST + t) * 2048 + 1024;
    float x1 = __half2float(pi[j]), x2 = __half2float(pi[j + 512]);
    const float inv_freq = powf(10000.f, -(float)(2 * j) * (1.f / 1024.f));
    float sn, cs; sincosf((float)t * inv_freq, &sn, &cs);
    float y1 = x1 * cs - x2 * sn, y2 = x2 * cs + x1 * sn;
    po[j] = y1; po[j + 512] = y2;
    ph[j] = __float2half_rn(y1); ph[j + 512] = __float2half_rn(y2);
}

__global__ void rope_q_kernel(const __half* __restrict__ in, __half* __restrict__ qcat,
                              const float* __restrict__ bias) {
    const int row = blockIdx.x; const int t = row % SEQ;
    const int j = threadIdx.x;
    const __half* pi = in + (size_t)row * 1024;
    __half* ph = qcat + (size_t)row * 2048 + 1024;
    float x1 = __half2float(pi[j]) + QSCALE * bias[j];
    float x2 = __half2float(pi[j + 512]) + QSCALE * bias[j + 512];
    const float inv_freq = powf(10000.f, -(float)(2 * j) * (1.f / 1024.f));
    float sn, cs; sincosf((float)t * inv_freq, &sn, &cs);
    ph[j]       = __float2half_rn(x1 * cs - x2 * sn);
    ph[j + 512] = __float2half_rn(x2 * cs + x1 * sn);
}

__global__ void softmax_kernel(const float* __restrict__ sc, __half* __restrict__ wh) {
    const int row = blockIdx.x;
    const int si  = row % SEQ;
    const int valid = si + PAST + 1;
    const float* p = sc + (size_t)row * STOT;
    __half* o = wh + (size_t)row * STOT;
    __shared__ float buf[STOT];
    __shared__ float red[8];
    const int tid = threadIdx.x;

    float mx = -3.4e38f;
    for (int j = tid; j < valid; j += 256) { float v = p[j]; buf[j] = v; mx = fmaxf(mx, v); }
    mx = blk_max(mx, red);
    float sum = 0.f;
    for (int j = tid; j < valid; j += 256) { float e = __expf(buf[j] - mx); buf[j] = e; sum += e; }
    sum = blk_sum(sum, red);
    const float inv = 1.f / sum;
    for (int j = tid; j < valid; j += 256) o[j] = __float2half_rn(buf[j] * inv);
    for (int j = valid + tid; j < STOT; j += 256) o[j] = __float2half_rn(0.f);
}

// ================= launch =================
extern "C" void kernel_launch(void* const* d_in, const int* in_sizes, int n_in,
                              void* d_out, int out_size)
{
    (void)in_sizes; (void)n_in; (void)out_size;
    const float* x        = (const float*)d_in[0];
    const float* kv_cache = (const float*)d_in[1];
    const float* kr_cache = (const float*)d_in[2];
    const float* Wq       = (const float*)d_in[3];
    const float* Wdkv     = (const float*)d_in[4];
    const float* Wuk      = (const float*)d_in[5];
    const float* Wuv      = (const float*)d_in[6];
    const float* Wo       = (const float*)d_in[7];
    const float* Wkr      = (const float*)d_in[8];
    const float* Wqr      = (const float*)d_in[9];
    const float* bqr      = (const float*)d_in[10];
    const float* ln_g     = (const float*)d_in[11];
    const float* ln_b     = (const float*)d_in[12];

    float* out = (float*)d_out;
    float* ckv = out + (size_t)B_ * SEQ * EDIM;
    float* kr  = ckv + (size_t)B_ * STOT * LDIM;

    __half *xh, *wqh, *wukh, *wdkvh, *wkrh, *wqrh, *woh, *wuvh, *wuvwoT, *absTh, *Kcat, *Qcat, *wh, *vTh;
    __half *cbuf, *krp, *qpre;
    float *sc;
    cudaGetSymbolAddress((void**)&xh,     g_xh);
    cudaGetSymbolAddress((void**)&wqh,    g_Wqh);
    cudaGetSymbolAddress((void**)&wukh,   g_Wukh);
    cudaGetSymbolAddress((void**)&wdkvh,  g_Wdkvh);
    cudaGetSymbolAddress((void**)&wkrh,   g_Wkrh);
    cudaGetSymbolAddress((void**)&wqrh,   g_Wqrh);
    cudaGetSymbolAddress((void**)&woh,    g_Woh);
    cudaGetSymbolAddress((void**)&wuvh,   g_Wuvh);
    cudaGetSymbolAddress((void**)&wuvwoT, g_WuvWoT);
    cudaGetSymbolAddress((void**)&absTh,  g_absTh);
    cudaGetSymbolAddress((void**)&cbuf,   g_c);
    cudaGetSymbolAddress((void**)&krp,    g_krp);
    cudaGetSymbolAddress((void**)&qpre,   g_qpre);
    cudaGetSymbolAddress((void**)&Kcat,   g_Kcat);
    cudaGetSymbolAddress((void**)&Qcat,   g_Qcat);
    cudaGetSymbolAddress((void**)&sc,     g_sc);
    cudaGetSymbolAddress((void**)&wh,     g_wh);
    cudaGetSymbolAddress((void**)&vTh,    g_vTh);

    cudaFuncSetAttribute(hgemm<false>, cudaFuncAttributeMaxDynamicSharedMemorySize, GEMM_SMEM);
    cudaFuncSetAttribute(hgemm<true>,  cudaFuncAttributeMaxDynamicSharedMemorySize, GEMM_SMEM);

    // ---- proven topology: 3 streams, 9 events, single-use, serial tail ----
    static cudaStream_t st[3] = {nullptr, nullptr, nullptr};
    static cudaEvent_t  ev[10] = {};
    if (st[0] == nullptr) {
        for (int i = 0; i < 3; i++) cudaStreamCreateWithFlags(&st[i], cudaStreamNonBlocking);
        for (int i = 0; i < 10; i++) cudaEventCreateWithFlags(&ev[i], cudaEventDisableTiming);
    }
    cudaEvent_t eFork = ev[0], eX = ev[1], eW = ev[2], eXa = ev[3], eT = ev[4],
                eRk = ev[5], eCc = ev[6], eLN = ev[7], eV = ev[8];

    const long long sL2 = (long long)SEQ * 2048;
    const long long SL2 = (long long)STOT * 2048;
    const long long sS  = (long long)SEQ * STOT;
    const long long sE  = (long long)SEQ * 1024;
    const long long ES  = (long long)EDIM * STOT;

    // ---------------- FORK ----------------
    cudaEventRecord(eFork, 0);
    for (int i = 0; i < 3; i++) cudaStreamWaitEvent(st[i], eFork, 0);

    cvt_f32_f16<<<4096, 256>>>(x, xh, (B_*SEQ*EDIM)/8);
    cudaEventRecord(eX, 0);

    // st[0]: weights cvt -> absT -> xa (Qcat left)
    cvt_weights6<<<3072, 256, 0, st[0]>>>(Wq, Wuk, Wdkv, Wkr, Wqr, Wo,
                                          wqh, wukh, wdkvh, wkrh, wqrh, woh);
    cudaEventRecord(eW, st[0]);
    hgemm<true><<<dim3(4, 4, 1), GEMM_THREADS, GEMM_SMEM, st[0]>>>(
        wukh, wqh, absTh, 1024, 1024, 1024, 0, 0, 0, 1024, 1024, 1024, 0);
    cudaStreamWaitEvent(st[0], eX, 0);
    hgemm<true><<<dim3(4, 32, 1), GEMM_THREADS, GEMM_SMEM, st[0]>>>(
        xh, absTh, Qcat, 8192, 1024, 1024, 0, 0, 0, 1024, 1024, 2048, 0);
    cudaEventRecord(eXa, st[0]);

    // st[1]: Wuv cvt -> WuvWoT = Wo @ Wuv^T, then krp (fp16) -> rope_k
    cvt_f32_f16<<<512, 256, 0, st[1]>>>(Wuv, wuvh, (LDIM*EDIM)/8);
    cudaStreamWaitEvent(st[1], eW, 0);
    hgemm<true><<<dim3(4, 4, 1), GEMM_THREADS, GEMM_SMEM, st[1]>>>(
        woh, wuvh, wuvwoT, 1024, 1024, 1024, 0, 0, 0, 1024, 1024, 1024, 0);
    cudaEventRecord(eT, st[1]);
    cudaStreamWaitEvent(st[1], eX, 0);
    hgemm<true><<<dim3(4, 32, 1), GEMM_THREADS, GEMM_SMEM, st[1]>>>(
        xh, wkrh, krp, 8192, 1024, 1024, 0, 0, 0, 1024, 1024, 1024, 0);
    rope_k_kernel<<<B_*SEQ, 512, 0, st[1]>>>(krp, kr, Kcat);
    cudaEventRecord(eRk, st[1]);

    // st[2]: cache copies
    copy_cache<<<B_*PAST, 256, 0, st[2]>>>(kv_cache, ckv, Kcat, 0);
    copy_cache<<<B_*PAST, 256, 0, st[2]>>>(kr_cache, kr,  Kcat, 1024);
    cudaEventRecord(eCc, st[2]);

    // main: c (fp16) -> LN -> qpre (fp16) -> rope_q (critical path)
    cudaStreamWaitEvent(0, eW, 0);
    hgemm<true><<<dim3(4, 32, 1), GEMM_THREADS, GEMM_SMEM>>>(
        xh, wdkvh, cbuf, 8192, 1024, 1024, 0, 0, 0, 1024, 1024, 1024, 0);
    layernorm_kernel<<<B_*SEQ, 256>>>(cbuf, ckv, Kcat, ln_g, ln_b);
    cudaEventRecord(eLN, 0);
    hgemm<true><<<dim3(4, 8, 4), GEMM_THREADS, GEMM_SMEM>>>(
        Kcat + (size_t)PAST * 2048, wqrh, qpre, 2048, 1024, 1024,
        SL2, 0, sE, 2048, 1024, 1024, 0);
    rope_q_kernel<<<B_*SEQ, 512>>>(qpre, Qcat, bqr);

    // st[2]: valueWT[E,S] = WuvWoT @ ckv^T (folded Wo) — overlaps scores
    cudaStreamWaitEvent(st[2], eLN, 0);
    cudaStreamWaitEvent(st[2], eT, 0);
    hgemm<true><<<dim3(16, 4, 4), GEMM_THREADS, GEMM_SMEM, st[2]>>>(
        wuvwoT, Kcat, vTh, 1024, 4096, 1024, 0, SL2, ES, 1024, 2048, 4096, 0);
    cudaEventRecord(eV, st[2]);

    // ---------------- JOIN for scores ----------------
    cudaStreamWaitEvent(0, eXa, 0);
    cudaStreamWaitEvent(0, eRk, 0);
    cudaStreamWaitEvent(0, eCc, 0);

    // scores = Qcat @ Kcat^T (pre-scaled; K=2048; causal tile skip)
    hgemm<false><<<dim3(16, 8, 4), GEMM_THREADS, GEMM_SMEM>>>(
        Qcat, Kcat, sc, 2048, 4096, 2048, sL2, SL2, sS, 2048, 2048, 4096, 1);

    softmax_kernel<<<B_*SEQ, 256>>>(sc, wh);

    // out = w @ valueWT^T  (fp32 directly to d_out; causal K-limit)
    cudaStreamWaitEvent(0, eV, 0);
    hgemm<false><<<dim3(4, 8, 4), GEMM_THREADS, GEMM_SMEM>>>(
        wh, vTh, out, 2048, 1024, 4096, sS, ES, sE, 4096, 4096, 1024, 2);
}